// round 4
// baseline (speedup 1.0000x reference)
#include <cuda_runtime.h>
#include <cstddef>

// Problem constants (fixed by the reference: B=4, T=2048, D=768, H=12)
#define BSZ   4
#define TLEN  2048
#define DMOD  768
#define NHEAD 12
#define HDIM  64
#define MROWS (BSZ * TLEN)       // 8192
#define QKVN  (3 * DMOD)         // 2304

// Scratch (no cudaMalloc allowed): qkv = [8192, 2304] f32, att = [8192, 768] f32
__device__ float g_qkv[(size_t)MROWS * QKVN];
__device__ float g_att[(size_t)MROWS * DMOD];

// ---------------------------------------------------------------------------
// SGEMM + bias: C[M,N] = A[M,K] @ B[K,N] + bias[N]
// BM=BN=128, BK=16, 256 threads, 8x8 microtile per thread.
// All problem dims divide tiles exactly (8192, 2304, 768 vs 128; 768 vs 16).
// ---------------------------------------------------------------------------
__global__ __launch_bounds__(256) void sgemm_bias_kernel(
    const float* __restrict__ A, const float* __restrict__ B,
    const float* __restrict__ bias, float* __restrict__ C,
    int M, int N, int K)
{
    __shared__ float As[16][128];   // As[k][m]
    __shared__ float Bs[16][128];   // Bs[k][n]

    const int tid = threadIdx.x;
    const int bm  = blockIdx.y;
    const int bn  = blockIdx.x;
    const int tr  = tid >> 4;       // 0..15 -> row group
    const int tc  = tid & 15;       // 0..15 -> col group

    float acc[8][8];
#pragma unroll
    for (int i = 0; i < 8; i++)
#pragma unroll
        for (int j = 0; j < 8; j++) acc[i][j] = 0.0f;

    const float* Ab = A + (size_t)bm * 128 * K;
    const float* Bb = B + (size_t)bn * 128;

    // A tile load mapping: 128x16 f32 = 512 float4, 2 per thread
    const int a_row = tid >> 2;     // 0..63 (+64 on i=1)
    const int a_c4  = tid & 3;      // 0..3
    // B tile load mapping: 16x128 f32 = 512 float4, 2 per thread
    const int b_row = tid >> 5;     // 0..7 (+8 on i=1)
    const int b_c4  = tid & 31;     // 0..31

    for (int k0 = 0; k0 < K; k0 += 16) {
#pragma unroll
        for (int i = 0; i < 2; i++) {
            int row = a_row + i * 64;
            float4 av = *(const float4*)(Ab + (size_t)row * K + k0 + a_c4 * 4);
            As[a_c4 * 4 + 0][row] = av.x;
            As[a_c4 * 4 + 1][row] = av.y;
            As[a_c4 * 4 + 2][row] = av.z;
            As[a_c4 * 4 + 3][row] = av.w;

            int brow = b_row + i * 8;
            float4 bv = *(const float4*)(Bb + (size_t)(k0 + brow) * N + b_c4 * 4);
            *(float4*)&Bs[brow][b_c4 * 4] = bv;
        }
        __syncthreads();

#pragma unroll
        for (int kk = 0; kk < 16; kk++) {
            float ar[8], br[8];
            *(float4*)&ar[0] = *(const float4*)&As[kk][tr * 8 + 0];
            *(float4*)&ar[4] = *(const float4*)&As[kk][tr * 8 + 4];
            *(float4*)&br[0] = *(const float4*)&Bs[kk][tc * 8 + 0];
            *(float4*)&br[4] = *(const float4*)&Bs[kk][tc * 8 + 4];
#pragma unroll
            for (int i = 0; i < 8; i++)
#pragma unroll
                for (int j = 0; j < 8; j++)
                    acc[i][j] += ar[i] * br[j];
        }
        __syncthreads();
    }

    // Epilogue: add bias, vectorized stores
#pragma unroll
    for (int i = 0; i < 8; i++) {
        int row = bm * 128 + tr * 8 + i;
#pragma unroll
        for (int j = 0; j < 8; j += 4) {
            int col = bn * 128 + tc * 8 + j;
            float4 o;
            o.x = acc[i][j + 0] + bias[col + 0];
            o.y = acc[i][j + 1] + bias[col + 1];
            o.z = acc[i][j + 2] + bias[col + 2];
            o.w = acc[i][j + 3] + bias[col + 3];
            *(float4*)(C + (size_t)row * N + col) = o;
        }
    }
}

// ---------------------------------------------------------------------------
// Causal flash attention.
// One thread per query row (BM = 128 rows/CTA, 128 threads).
// K/V blocks of 64 rows staged in smem; smem reads are warp-broadcast
// (all lanes in a warp share the same key index), so the kernel is FMA-bound.
// q (scaled) and the O accumulator (64 floats) live entirely in registers.
// Online softmax in chunks of 16 keys to bound register pressure.
// ---------------------------------------------------------------------------
__global__ __launch_bounds__(128) void attn_kernel(
    const float* __restrict__ qkv, float* __restrict__ att)
{
    const int qblk = blockIdx.x;            // 0..15
    const int h    = blockIdx.y;            // 0..11
    const int b    = blockIdx.z;            // 0..3
    const int tid  = threadIdx.x;           // 0..127
    const int gq   = qblk * 128 + tid;      // global query index in [0, T)

    __shared__ float Ks[64][64];
    __shared__ float Vs[64][64];

    const float scale = 0.125f;             // 1/sqrt(64)

    // Load q row (pre-scaled) into registers
    float q[64];
    {
        const float* qrow = qkv + ((size_t)(b * TLEN + gq)) * QKVN + h * HDIM;
#pragma unroll
        for (int d = 0; d < 64; d += 4) {
            float4 t = *(const float4*)(qrow + d);
            q[d + 0] = t.x * scale;
            q[d + 1] = t.y * scale;
            q[d + 2] = t.z * scale;
            q[d + 3] = t.w * scale;
        }
    }

    float o[64];
#pragma unroll
    for (int d = 0; d < 64; d++) o[d] = 0.0f;
    float m = -1e30f;
    float l = 0.0f;

    const int nkey = (qblk + 1) * 128;      // causal: keys [0, nkey)

    for (int j0 = 0; j0 < nkey; j0 += 64) {
        // Stage K and V blocks: 64x64 f32 each = 1024 float4 per tile,
        // 8 float4 per thread per tile. Coalesced (256B runs per row).
#pragma unroll
        for (int i = 0; i < 8; i++) {
            int idx = i * 128 + tid;        // 0..1023
            int r   = idx >> 4;             // 0..63
            int c4  = idx & 15;             // 0..15
            size_t base = ((size_t)(b * TLEN + j0 + r)) * QKVN + h * HDIM + c4 * 4;
            *(float4*)&Ks[r][c4 * 4] = *(const float4*)(qkv + base + DMOD);
            *(float4*)&Vs[r][c4 * 4] = *(const float4*)(qkv + base + 2 * DMOD);
        }
        __syncthreads();

        const bool need_mask = (j0 + 64 > qblk * 128);

#pragma unroll 1
        for (int c = 0; c < 4; c++) {
            float s[16];
            // Scores for 16 keys
#pragma unroll
            for (int j = 0; j < 16; j++) {
                int jj = c * 16 + j;
                float sum = 0.0f;
#pragma unroll
                for (int d = 0; d < 64; d += 4) {
                    float4 kv = *(const float4*)&Ks[jj][d];
                    sum += q[d + 0] * kv.x + q[d + 1] * kv.y
                         + q[d + 2] * kv.z + q[d + 3] * kv.w;
                }
                if (need_mask && (j0 + jj > gq)) sum = -1e30f;
                s[j] = sum;
            }
            // Online softmax update
            float cm = s[0];
#pragma unroll
            for (int j = 1; j < 16; j++) cm = fmaxf(cm, s[j]);
            float mn = fmaxf(m, cm);
            float corr = __expf(m - mn);
            l *= corr;
#pragma unroll
            for (int d = 0; d < 64; d++) o[d] *= corr;
            m = mn;
            // Accumulate P @ V
#pragma unroll
            for (int j = 0; j < 16; j++) {
                float p = __expf(s[j] - m);
                l += p;
                int jj = c * 16 + j;
#pragma unroll
                for (int d = 0; d < 64; d += 4) {
                    float4 vv = *(const float4*)&Vs[jj][d];
                    o[d + 0] += p * vv.x;
                    o[d + 1] += p * vv.y;
                    o[d + 2] += p * vv.z;
                    o[d + 3] += p * vv.w;
                }
            }
        }
        __syncthreads();
    }

    // Normalize and write back in [B, T, H*hd] layout (ready for W_o GEMM)
    const float inv = 1.0f / l;
    float* orow = att + ((size_t)(b * TLEN + gq)) * DMOD + h * HDIM;
#pragma unroll
    for (int d = 0; d < 64; d += 4) {
        float4 t;
        t.x = o[d + 0] * inv;
        t.y = o[d + 1] * inv;
        t.z = o[d + 2] * inv;
        t.w = o[d + 3] * inv;
        *(float4*)(orow + d) = t;
    }
}

// ---------------------------------------------------------------------------
// Launch: QKV GEMM -> flash attention -> output GEMM. Graph-capturable:
// kernel launches only, scratch in __device__ globals, default stream.
// ---------------------------------------------------------------------------
extern "C" void kernel_launch(void* const* d_in, const int* in_sizes, int n_in,
                              void* d_out, int out_size)
{
    (void)in_sizes; (void)n_in; (void)out_size;
    const float* x     = (const float*)d_in[0];
    const float* W_qkv = (const float*)d_in[1];
    const float* b_qkv = (const float*)d_in[2];
    const float* W_o   = (const float*)d_in[3];
    const float* b_o   = (const float*)d_in[4];
    float* out = (float*)d_out;

    float* qkv_ptr = nullptr;
    float* att_ptr = nullptr;
    cudaGetSymbolAddress((void**)&qkv_ptr, g_qkv);
    cudaGetSymbolAddress((void**)&att_ptr, g_att);

    // 1) qkv = x @ W_qkv + b_qkv    [8192, 2304]
    {
        dim3 grid(QKVN / 128, MROWS / 128);   // (18, 64)
        sgemm_bias_kernel<<<grid, 256>>>(x, W_qkv, b_qkv, qkv_ptr,
                                         MROWS, QKVN, DMOD);
    }
    // 2) causal flash attention     [8192, 768]
    {
        dim3 grid(TLEN / 128, NHEAD, BSZ);    // (16, 12, 4)
        attn_kernel<<<grid, 128>>>(qkv_ptr, att_ptr);
    }
    // 3) out = att @ W_o + b_o      [8192, 768]
    {
        dim3 grid(DMOD / 128, MROWS / 128);   // (6, 64)
        sgemm_bias_kernel<<<grid, 256>>>(att_ptr, W_o, b_o, out,
                                         MROWS, DMOD, DMOD);
    }
}

// round 5
// speedup vs baseline: 1.2318x; 1.2318x over previous
#include <cuda_runtime.h>
#include <cstddef>

// Problem constants (fixed by the reference: B=4, T=2048, D=768, H=12)
#define BSZ   4
#define TLEN  2048
#define DMOD  768
#define NHEAD 12
#define HDIM  64
#define MROWS (BSZ * TLEN)       // 8192
#define QKVN  (3 * DMOD)         // 2304

// Scratch (no cudaMalloc allowed): qkv = [8192, 2304] f32, att = [8192, 768] f32
__device__ float g_qkv[(size_t)MROWS * QKVN];
__device__ float g_att[(size_t)MROWS * DMOD];

// ---------------------------------------------------------------------------
// SGEMM + bias: C[M,N] = A[M,K] @ B[K,N] + bias[N]
// BM=BN=128, BK=16, 256 threads, 8x8 microtile per thread.
// ---------------------------------------------------------------------------
__global__ __launch_bounds__(256) void sgemm_bias_kernel(
    const float* __restrict__ A, const float* __restrict__ B,
    const float* __restrict__ bias, float* __restrict__ C,
    int M, int N, int K)
{
    __shared__ float As[16][128];   // As[k][m]
    __shared__ float Bs[16][128];   // Bs[k][n]

    const int tid = threadIdx.x;
    const int bm  = blockIdx.y;
    const int bn  = blockIdx.x;
    const int tr  = tid >> 4;
    const int tc  = tid & 15;

    float acc[8][8];
#pragma unroll
    for (int i = 0; i < 8; i++)
#pragma unroll
        for (int j = 0; j < 8; j++) acc[i][j] = 0.0f;

    const float* Ab = A + (size_t)bm * 128 * K;
    const float* Bb = B + (size_t)bn * 128;

    const int a_row = tid >> 2;
    const int a_c4  = tid & 3;
    const int b_row = tid >> 5;
    const int b_c4  = tid & 31;

    for (int k0 = 0; k0 < K; k0 += 16) {
#pragma unroll
        for (int i = 0; i < 2; i++) {
            int row = a_row + i * 64;
            float4 av = *(const float4*)(Ab + (size_t)row * K + k0 + a_c4 * 4);
            As[a_c4 * 4 + 0][row] = av.x;
            As[a_c4 * 4 + 1][row] = av.y;
            As[a_c4 * 4 + 2][row] = av.z;
            As[a_c4 * 4 + 3][row] = av.w;

            int brow = b_row + i * 8;
            float4 bv = *(const float4*)(Bb + (size_t)(k0 + brow) * N + b_c4 * 4);
            *(float4*)&Bs[brow][b_c4 * 4] = bv;
        }
        __syncthreads();

#pragma unroll
        for (int kk = 0; kk < 16; kk++) {
            float ar[8], br[8];
            *(float4*)&ar[0] = *(const float4*)&As[kk][tr * 8 + 0];
            *(float4*)&ar[4] = *(const float4*)&As[kk][tr * 8 + 4];
            *(float4*)&br[0] = *(const float4*)&Bs[kk][tc * 8 + 0];
            *(float4*)&br[4] = *(const float4*)&Bs[kk][tc * 8 + 4];
#pragma unroll
            for (int i = 0; i < 8; i++)
#pragma unroll
                for (int j = 0; j < 8; j++)
                    acc[i][j] += ar[i] * br[j];
        }
        __syncthreads();
    }

#pragma unroll
    for (int i = 0; i < 8; i++) {
        int row = bm * 128 + tr * 8 + i;
#pragma unroll
        for (int j = 0; j < 8; j += 4) {
            int col = bn * 128 + tc * 8 + j;
            float4 o;
            o.x = acc[i][j + 0] + bias[col + 0];
            o.y = acc[i][j + 1] + bias[col + 1];
            o.z = acc[i][j + 2] + bias[col + 2];
            o.w = acc[i][j + 3] + bias[col + 3];
            *(float4*)(C + (size_t)row * N + col) = o;
        }
    }
}

// ---------------------------------------------------------------------------
// GEMM-shaped causal flash attention.
// CTA: 128 queries x full head. Key blocks of 64. 256 threads.
// Unified thread grid: qr = tid>>3 (32 groups of 4 queries), kc/dc = tid&7.
// S-phase: s[4][8] microtile GEMM from d-major Qs/Ks (3 LDS.128 / 32 FFMA).
// Softmax stats (m, l, corr) entirely in registers; row reduce = 3 shfl.
// P exchanged via smem Ps[128][68]; PV-phase: o[4][8] microtile GEMM.
// ---------------------------------------------------------------------------
struct AttnSmem {
    float Qs[64][128];   // d-major Q, prescaled   (32 KB)
    float Ks[64][64];    // d-major K              (16 KB)
    float Vs[64][64];    // row-major V            (16 KB)
    float Ps[128][68];   // P tile, padded stride  (34 KB)
};

__global__ __launch_bounds__(256, 2) void attn_kernel(
    const float* __restrict__ qkv, float* __restrict__ att)
{
    extern __shared__ char smem_raw[];
    AttnSmem& S = *reinterpret_cast<AttnSmem*>(smem_raw);

    const int qb  = blockIdx.x;         // 0..15
    const int h   = blockIdx.y;         // 0..11
    const int b   = blockIdx.z;         // 0..3
    const int tid = threadIdx.x;
    const int qr  = tid >> 3;           // 0..31
    const int kc  = tid & 7;            // 0..7 (key group in S, dim group in PV)

    // Stage Q (prescaled) d-major: Qs[d][q]. 2048 float4 loads, 8/thread,
    // 32B coalesced runs over 16 rows per warp; STS 2-way conflict.
    {
        const float scale = 0.125f;     // 1/sqrt(64)
#pragma unroll
        for (int i = 0; i < 8; i++) {
            int f  = i * 256 + tid;
            int c4 = (f >> 8) * 2 + (f & 1);      // 0..15
            int r  = (f >> 1) & 127;              // 0..127
            float4 v = *(const float4*)(qkv +
                ((size_t)(b * TLEN + qb * 128 + r)) * QKVN + h * HDIM + c4 * 4);
            S.Qs[c4 * 4 + 0][r] = v.x * scale;
            S.Qs[c4 * 4 + 1][r] = v.y * scale;
            S.Qs[c4 * 4 + 2][r] = v.z * scale;
            S.Qs[c4 * 4 + 3][r] = v.w * scale;
        }
    }

    float o[4][8];
#pragma unroll
    for (int i = 0; i < 4; i++)
#pragma unroll
        for (int j = 0; j < 8; j++) o[i][j] = 0.0f;
    float m[4] = {-1e30f, -1e30f, -1e30f, -1e30f};
    float l[4] = {0.0f, 0.0f, 0.0f, 0.0f};

    const int nblk = 2 * qb + 2;        // key blocks of 64 covering [0,(qb+1)*128)

    for (int kb = 0; kb < nblk; kb++) {
        const int j0 = kb * 64;
        __syncthreads();                // prior PV readers done with Vs/Ps

        // Stage K d-major + V row-major (1024 float4 each, 4/thread)
#pragma unroll
        for (int i = 0; i < 4; i++) {
            int f  = i * 256 + tid;
            int c4 = (f >> 7) * 2 + (f & 1);      // 0..15
            int r  = (f >> 1) & 63;               // 0..63
            size_t rowb = ((size_t)(b * TLEN + j0 + r)) * QKVN + h * HDIM;
            float4 kv = *(const float4*)(qkv + rowb + DMOD + c4 * 4);
            S.Ks[c4 * 4 + 0][r] = kv.x;
            S.Ks[c4 * 4 + 1][r] = kv.y;
            S.Ks[c4 * 4 + 2][r] = kv.z;
            S.Ks[c4 * 4 + 3][r] = kv.w;

            int rv  = f >> 4;                     // 0..63
            int c4v = f & 15;                     // 0..15
            size_t rowv = ((size_t)(b * TLEN + j0 + rv)) * QKVN
                        + h * HDIM + 2 * DMOD;
            *(float4*)&S.Vs[rv][c4v * 4] = *(const float4*)(qkv + rowv + c4v * 4);
        }
        __syncthreads();

        // ---- S = Q K^T microtile (4 queries x 8 keys per thread) ----
        float s[4][8];
#pragma unroll
        for (int i = 0; i < 4; i++)
#pragma unroll
            for (int j = 0; j < 8; j++) s[i][j] = 0.0f;

#pragma unroll 8
        for (int d = 0; d < 64; d++) {
            float ar[4], br[8];
            *(float4*)&ar[0] = *(const float4*)&S.Qs[d][qr * 4];
            *(float4*)&br[0] = *(const float4*)&S.Ks[d][kc * 8 + 0];
            *(float4*)&br[4] = *(const float4*)&S.Ks[d][kc * 8 + 4];
#pragma unroll
            for (int i = 0; i < 4; i++)
#pragma unroll
                for (int j = 0; j < 8; j++)
                    s[i][j] += ar[i] * br[j];
        }

        // Causal mask: only the blocks overlapping the query range
        if (kb >= 2 * qb) {
#pragma unroll
            for (int i = 0; i < 4; i++) {
                int q = qb * 128 + qr * 4 + i;
#pragma unroll
                for (int j = 0; j < 8; j++)
                    if (j0 + kc * 8 + j > q) s[i][j] = -1e30f;
            }
        }

        // ---- Online softmax (stats in registers, reduce over 8 kc lanes) ----
        float corr[4];
#pragma unroll
        for (int i = 0; i < 4; i++) {
            float mx = s[i][0];
#pragma unroll
            for (int j = 1; j < 8; j++) mx = fmaxf(mx, s[i][j]);
            mx = fmaxf(mx, __shfl_xor_sync(0xffffffffu, mx, 1));
            mx = fmaxf(mx, __shfl_xor_sync(0xffffffffu, mx, 2));
            mx = fmaxf(mx, __shfl_xor_sync(0xffffffffu, mx, 4));
            float mn = fmaxf(m[i], mx);
            corr[i] = __expf(m[i] - mn);
            m[i] = mn;
            float sum = 0.0f;
#pragma unroll
            for (int j = 0; j < 8; j++) {
                float p = __expf(s[i][j] - mn);
                s[i][j] = p;
                sum += p;
            }
            sum += __shfl_xor_sync(0xffffffffu, sum, 1);
            sum += __shfl_xor_sync(0xffffffffu, sum, 2);
            sum += __shfl_xor_sync(0xffffffffu, sum, 4);
            l[i] = l[i] * corr[i] + sum;
            // Exchange P via smem
            *(float4*)&S.Ps[qr * 4 + i][kc * 8 + 0] = *(float4*)&s[i][0];
            *(float4*)&S.Ps[qr * 4 + i][kc * 8 + 4] = *(float4*)&s[i][4];
        }
        __syncthreads();

        // Rescale O accumulator
#pragma unroll
        for (int i = 0; i < 4; i++)
#pragma unroll
            for (int j = 0; j < 8; j++) o[i][j] *= corr[i];

        // ---- O += P V microtile (4 queries x 8 dims per thread) ----
#pragma unroll 4
        for (int k = 0; k < 64; k++) {
            float br[8];
            *(float4*)&br[0] = *(const float4*)&S.Vs[k][kc * 8 + 0];
            *(float4*)&br[4] = *(const float4*)&S.Vs[k][kc * 8 + 4];
#pragma unroll
            for (int i = 0; i < 4; i++) {
                float a = S.Ps[qr * 4 + i][k];
#pragma unroll
                for (int j = 0; j < 8; j++)
                    o[i][j] += a * br[j];
            }
        }
    }

    // Epilogue: normalize, write [B,T,H*hd] layout
#pragma unroll
    for (int i = 0; i < 4; i++) {
        float inv = 1.0f / l[i];
        float* orow = att + ((size_t)(b * TLEN + qb * 128 + qr * 4 + i)) * DMOD
                    + h * HDIM + kc * 8;
        float4 t0, t1;
        t0.x = o[i][0] * inv; t0.y = o[i][1] * inv;
        t0.z = o[i][2] * inv; t0.w = o[i][3] * inv;
        t1.x = o[i][4] * inv; t1.y = o[i][5] * inv;
        t1.z = o[i][6] * inv; t1.w = o[i][7] * inv;
        *(float4*)(orow + 0) = t0;
        *(float4*)(orow + 4) = t1;
    }
}

// ---------------------------------------------------------------------------
// Launch: QKV GEMM -> flash attention -> output GEMM.
// ---------------------------------------------------------------------------
extern "C" void kernel_launch(void* const* d_in, const int* in_sizes, int n_in,
                              void* d_out, int out_size)
{
    (void)in_sizes; (void)n_in; (void)out_size;
    const float* x     = (const float*)d_in[0];
    const float* W_qkv = (const float*)d_in[1];
    const float* b_qkv = (const float*)d_in[2];
    const float* W_o   = (const float*)d_in[3];
    const float* b_o   = (const float*)d_in[4];
    float* out = (float*)d_out;

    float* qkv_ptr = nullptr;
    float* att_ptr = nullptr;
    cudaGetSymbolAddress((void**)&qkv_ptr, g_qkv);
    cudaGetSymbolAddress((void**)&att_ptr, g_att);

    // 1) qkv = x @ W_qkv + b_qkv    [8192, 2304]
    {
        dim3 grid(QKVN / 128, MROWS / 128);
        sgemm_bias_kernel<<<grid, 256>>>(x, W_qkv, b_qkv, qkv_ptr,
                                         MROWS, QKVN, DMOD);
    }
    // 2) causal flash attention     [8192, 768]
    {
        static int smem_set = 0;
        int smem_bytes = (int)sizeof(AttnSmem);
        if (!smem_set) {
            cudaFuncSetAttribute(attn_kernel,
                                 cudaFuncAttributeMaxDynamicSharedMemorySize,
                                 smem_bytes);
            smem_set = 1;
        }
        dim3 grid(TLEN / 128, NHEAD, BSZ);
        attn_kernel<<<grid, 256, smem_bytes>>>(qkv_ptr, att_ptr);
    }
    // 3) out = att @ W_o + b_o      [8192, 768]
    {
        dim3 grid(DMOD / 128, MROWS / 128);
        sgemm_bias_kernel<<<grid, 256>>>(att_ptr, W_o, b_o, out,
                                         MROWS, DMOD, DMOD);
    }
}

// round 6
// speedup vs baseline: 1.7796x; 1.4447x over previous
#include <cuda_runtime.h>
#include <mma.h>
#include <cstddef>

using namespace nvcuda;

// Problem constants (fixed by the reference: B=4, T=2048, D=768, H=12)
#define BSZ   4
#define TLEN  2048
#define DMOD  768
#define NHEAD 12
#define HDIM  64
#define MROWS (BSZ * TLEN)       // 8192
#define QKVN  (3 * DMOD)         // 2304

// Scratch (no cudaMalloc allowed)
__device__ float g_qkv[(size_t)MROWS * QKVN];
__device__ float g_att[(size_t)MROWS * DMOD];

__device__ __forceinline__ float to_tf32(float x) {
    float r;
    asm("cvt.rna.tf32.f32 %0, %1;" : "=f"(r) : "f"(x));
    return r;
}

// ---------------------------------------------------------------------------
// TF32 wmma GEMM + bias: C[M,N] = A[M,K] @ B[K,N] + bias[N]
// BM=BN=128, BK=32, 256 threads (8 warps), warp tile 64x32 = 4x2 wmma tiles.
// Bias is pre-loaded into the accumulators via a broadcast smem tile.
// ---------------------------------------------------------------------------
#define GA_ST 36     // As row stride (floats), mult of 4, 144B mult of 16
#define GB_ST 136    // Bs row stride (floats), 544B mult of 16

__global__ __launch_bounds__(256) void gemm_tf32_bias(
    const float* __restrict__ A, const float* __restrict__ B,
    const float* __restrict__ bias, float* __restrict__ C,
    int M, int N, int K)
{
    __shared__ float As[128][GA_ST];   // 18 KB
    __shared__ float Bs[32][GB_ST];    // 17 KB

    const int tid   = threadIdx.x;
    const int wid   = tid >> 5;
    const int warpM = wid >> 2;        // 0..1
    const int warpN = wid & 3;         // 0..3
    const int bm    = blockIdx.y;
    const int bn    = blockIdx.x;

    wmma::fragment<wmma::accumulator, 16, 16, 8, float> c[4][2];

    // ---- bias init: replicate bias slice into 16 rows of Bs, load c frags
    for (int f = tid; f < 16 * 32; f += 256) {
        int r = f >> 5, c4 = f & 31;
        *(float4*)&Bs[r][c4 * 4] = *(const float4*)(bias + bn * 128 + c4 * 4);
    }
    __syncthreads();
#pragma unroll
    for (int i = 0; i < 4; i++)
#pragma unroll
        for (int j = 0; j < 2; j++)
            wmma::load_matrix_sync(c[i][j], &Bs[0][warpN * 32 + j * 16],
                                   GB_ST, wmma::mem_row_major);
    __syncthreads();

    const float* Ab = A + (size_t)bm * 128 * K;
    const float* Bb = B + (size_t)bn * 128;

    for (int k0 = 0; k0 < K; k0 += 32) {
        // Stage A tile 128x32 (1024 float4, 4/thread) and B tile 32x128
#pragma unroll
        for (int i = 0; i < 4; i++) {
            int f = i * 256 + tid;
            int ar = f >> 3, ac4 = f & 7;
            float4 av = *(const float4*)(Ab + (size_t)ar * K + k0 + ac4 * 4);
            av.x = to_tf32(av.x); av.y = to_tf32(av.y);
            av.z = to_tf32(av.z); av.w = to_tf32(av.w);
            *(float4*)&As[ar][ac4 * 4] = av;

            int br = f >> 5, bc4 = f & 31;
            float4 bv = *(const float4*)(Bb + (size_t)(k0 + br) * N + bc4 * 4);
            bv.x = to_tf32(bv.x); bv.y = to_tf32(bv.y);
            bv.z = to_tf32(bv.z); bv.w = to_tf32(bv.w);
            *(float4*)&Bs[br][bc4 * 4] = bv;
        }
        __syncthreads();

#pragma unroll
        for (int ks = 0; ks < 4; ks++) {
            wmma::fragment<wmma::matrix_a, 16, 16, 8, wmma::precision::tf32,
                           wmma::row_major> a[4];
            wmma::fragment<wmma::matrix_b, 16, 16, 8, wmma::precision::tf32,
                           wmma::row_major> b[2];
#pragma unroll
            for (int i = 0; i < 4; i++)
                wmma::load_matrix_sync(a[i], &As[warpM * 64 + i * 16][ks * 8],
                                       GA_ST);
#pragma unroll
            for (int j = 0; j < 2; j++)
                wmma::load_matrix_sync(b[j], &Bs[ks * 8][warpN * 32 + j * 16],
                                       GB_ST);
#pragma unroll
            for (int i = 0; i < 4; i++)
#pragma unroll
                for (int j = 0; j < 2; j++)
                    wmma::mma_sync(c[i][j], a[i], b[j], c[i][j]);
        }
        __syncthreads();
    }

    // ---- epilogue: store accumulators straight to C
#pragma unroll
    for (int i = 0; i < 4; i++)
#pragma unroll
        for (int j = 0; j < 2; j++) {
            size_t row = (size_t)(bm * 128 + warpM * 64 + i * 16);
            int    col = bn * 128 + warpN * 32 + j * 16;
            wmma::store_matrix_sync(C + row * N + col, c[i][j], N,
                                    wmma::mem_row_major);
        }
}

// ---------------------------------------------------------------------------
// TF32 wmma causal flash attention.
// CTA: 128 queries x one head; key blocks of 64; 256 threads (8 warps).
// Warp w owns query rows [w*16, w*16+16). Q lives in 8 preloaded a-frags.
// Per block: S-mma -> Ss; softmax in smem (stats in regs, 2 threads/row);
// O rescale in smem; PV-mma with accumulator load/store via Os.
// ---------------------------------------------------------------------------
#define AS 68        // stride (floats) for 64-wide smem tiles; 272B/row

struct AttnSmem {
    float Ks[64][AS];     // tf32 K block
    float Vs[64][AS];     // tf32 V block
    float Ss[128][AS];    // S scores / P probs (also initial Q staging)
    float Os[128][AS];    // O accumulator
};                        // 104448 bytes

__global__ __launch_bounds__(256, 2) void attn_tf32_kernel(
    const float* __restrict__ qkv, float* __restrict__ att)
{
    extern __shared__ char smem_raw[];
    AttnSmem& S = *reinterpret_cast<AttnSmem*>(smem_raw);

    const int qb  = blockIdx.x;        // 0..15
    const int h   = blockIdx.y;        // 0..11
    const int b   = blockIdx.z;        // 0..3
    const int tid = threadIdx.x;
    const int wid = tid >> 5;

    // Softmax row ownership: 2 threads per row
    const int row  = tid >> 1;         // 0..127
    const int half = tid & 1;          // 0..1 -> cols half*32..+32
    const int gq   = qb * 128 + row;

    // ---- Stage Q (prescaled, tf32) into Ss; zero Os
    {
        const float scale = 0.125f;    // 1/sqrt(64)
#pragma unroll
        for (int i = 0; i < 8; i++) {
            int f = i * 256 + tid;     // 2048 float4
            int r = f >> 4, c4 = f & 15;
            float4 v = *(const float4*)(qkv +
                ((size_t)(b * TLEN + qb * 128 + r)) * QKVN + h * HDIM + c4 * 4);
            v.x = to_tf32(v.x * scale); v.y = to_tf32(v.y * scale);
            v.z = to_tf32(v.z * scale); v.w = to_tf32(v.w * scale);
            *(float4*)&S.Ss[r][c4 * 4] = v;
        }
        float4 z = make_float4(0.f, 0.f, 0.f, 0.f);
        float4* Oflat = (float4*)&S.Os[0][0];
        for (int i = tid; i < 128 * AS / 4; i += 256) Oflat[i] = z;
    }
    __syncthreads();

    // ---- Preload Q fragments (loop-invariant). Warp reads only its own
    // strip, which only it overwrites later -> no extra barrier needed.
    wmma::fragment<wmma::matrix_a, 16, 16, 8, wmma::precision::tf32,
                   wmma::row_major> qa[8];
#pragma unroll
    for (int kk = 0; kk < 8; kk++)
        wmma::load_matrix_sync(qa[kk], &S.Ss[wid * 16][kk * 8], AS);

    float mrow = -1e30f, lrow = 0.0f;  // per-row stats (duplicated x2 threads)

    const int nblk = 2 * qb + 2;
    for (int kb = 0; kb < nblk; kb++) {
        const int j0 = kb * 64;
        __syncthreads();               // prior PV reads of Ks/Vs/Ss done

        // ---- Stage K, V (tf32): 64x16 float4 each, 4/thread
#pragma unroll
        for (int i = 0; i < 4; i++) {
            int f = i * 256 + tid;
            int r = f >> 4, c4 = f & 15;
            size_t base = ((size_t)(b * TLEN + j0 + r)) * QKVN + h * HDIM;
            float4 kv = *(const float4*)(qkv + base + DMOD + c4 * 4);
            kv.x = to_tf32(kv.x); kv.y = to_tf32(kv.y);
            kv.z = to_tf32(kv.z); kv.w = to_tf32(kv.w);
            *(float4*)&S.Ks[r][c4 * 4] = kv;
            float4 vv = *(const float4*)(qkv + base + 2 * DMOD + c4 * 4);
            vv.x = to_tf32(vv.x); vv.y = to_tf32(vv.y);
            vv.z = to_tf32(vv.z); vv.w = to_tf32(vv.w);
            *(float4*)&S.Vs[r][c4 * 4] = vv;
        }
        __syncthreads();

        // ---- S = Q K^T  (per warp: 16 rows x 64 keys)
        {
            wmma::fragment<wmma::accumulator, 16, 16, 8, float> sc[4];
#pragma unroll
            for (int j = 0; j < 4; j++) wmma::fill_fragment(sc[j], 0.0f);
#pragma unroll
            for (int kk = 0; kk < 8; kk++) {
#pragma unroll
                for (int j = 0; j < 4; j++) {
                    wmma::fragment<wmma::matrix_b, 16, 16, 8,
                                   wmma::precision::tf32, wmma::col_major> kf;
                    // B[d][key] = Ks[key][d] -> col_major from row-major K
                    wmma::load_matrix_sync(kf, &S.Ks[j * 16][kk * 8], AS);
                    wmma::mma_sync(sc[j], qa[kk], kf, sc[j]);
                }
            }
#pragma unroll
            for (int j = 0; j < 4; j++)
                wmma::store_matrix_sync(&S.Ss[wid * 16][j * 16], sc[j], AS,
                                        wmma::mem_row_major);
        }
        __syncthreads();

        // ---- Softmax on Ss rows (thread handles 32 cols of its row)
        {
            const bool diag = (kb >= 2 * qb);
            float* srow = &S.Ss[row][half * 32];
            // pass 1: masked max
            float mx = -1e30f;
#pragma unroll
            for (int c4 = 0; c4 < 8; c4++) {
                float4 v = *(float4*)(srow + c4 * 4);
                if (diag) {
                    int jg = j0 + half * 32 + c4 * 4;
                    if (jg + 0 > gq) v.x = -1e30f;
                    if (jg + 1 > gq) v.y = -1e30f;
                    if (jg + 2 > gq) v.z = -1e30f;
                    if (jg + 3 > gq) v.w = -1e30f;
                    *(float4*)(srow + c4 * 4) = v;   // persist mask for pass 2
                }
                mx = fmaxf(mx, fmaxf(fmaxf(v.x, v.y), fmaxf(v.z, v.w)));
            }
            mx = fmaxf(mx, __shfl_xor_sync(0xffffffffu, mx, 1));
            float mn   = fmaxf(mrow, mx);
            float corr = __expf(mrow - mn);
            mrow = mn;
            // pass 2: exp, sum, store P (tf32)
            float sum = 0.0f;
#pragma unroll
            for (int c4 = 0; c4 < 8; c4++) {
                float4 v = *(float4*)(srow + c4 * 4);
                v.x = __expf(v.x - mn); v.y = __expf(v.y - mn);
                v.z = __expf(v.z - mn); v.w = __expf(v.w - mn);
                sum += (v.x + v.y) + (v.z + v.w);
                v.x = to_tf32(v.x); v.y = to_tf32(v.y);
                v.z = to_tf32(v.z); v.w = to_tf32(v.w);
                *(float4*)(srow + c4 * 4) = v;
            }
            sum += __shfl_xor_sync(0xffffffffu, sum, 1);
            lrow = lrow * corr + sum;
            // rescale O accumulator row
            float* orow = &S.Os[row][half * 32];
#pragma unroll
            for (int c4 = 0; c4 < 8; c4++) {
                float4 v = *(float4*)(orow + c4 * 4);
                v.x *= corr; v.y *= corr; v.z *= corr; v.w *= corr;
                *(float4*)(orow + c4 * 4) = v;
            }
        }
        __syncthreads();

        // ---- O += P V  (per warp: 16 rows x 64 dims, accumulate via Os)
        {
            wmma::fragment<wmma::accumulator, 16, 16, 8, float> oc[4];
#pragma unroll
            for (int j = 0; j < 4; j++)
                wmma::load_matrix_sync(oc[j], &S.Os[wid * 16][j * 16], AS,
                                       wmma::mem_row_major);
#pragma unroll
            for (int kk = 0; kk < 8; kk++) {
                wmma::fragment<wmma::matrix_a, 16, 16, 8,
                               wmma::precision::tf32, wmma::row_major> pa;
                wmma::load_matrix_sync(pa, &S.Ss[wid * 16][kk * 8], AS);
#pragma unroll
                for (int j = 0; j < 4; j++) {
                    wmma::fragment<wmma::matrix_b, 16, 16, 8,
                                   wmma::precision::tf32, wmma::row_major> vf;
                    wmma::load_matrix_sync(vf, &S.Vs[kk * 8][j * 16], AS);
                    wmma::mma_sync(oc[j], pa, vf, oc[j]);
                }
            }
#pragma unroll
            for (int j = 0; j < 4; j++)
                wmma::store_matrix_sync(&S.Os[wid * 16][j * 16], oc[j], AS,
                                        wmma::mem_row_major);
        }
    }
    __syncthreads();

    // ---- Epilogue: normalize rows, write [B,T,H*hd]
    {
        float inv = 1.0f / lrow;
        float* orow = &S.Os[row][half * 32];
        float* dst  = att + ((size_t)(b * TLEN + gq)) * DMOD + h * HDIM
                    + half * 32;
#pragma unroll
        for (int c4 = 0; c4 < 8; c4++) {
            float4 v = *(float4*)(orow + c4 * 4);
            v.x *= inv; v.y *= inv; v.z *= inv; v.w *= inv;
            *(float4*)(dst + c4 * 4) = v;
        }
    }
}

// ---------------------------------------------------------------------------
// Launch: QKV GEMM -> flash attention -> output GEMM.
// ---------------------------------------------------------------------------
extern "C" void kernel_launch(void* const* d_in, const int* in_sizes, int n_in,
                              void* d_out, int out_size)
{
    (void)in_sizes; (void)n_in; (void)out_size;
    const float* x     = (const float*)d_in[0];
    const float* W_qkv = (const float*)d_in[1];
    const float* b_qkv = (const float*)d_in[2];
    const float* W_o   = (const float*)d_in[3];
    const float* b_o   = (const float*)d_in[4];
    float* out = (float*)d_out;

    float* qkv_ptr = nullptr;
    float* att_ptr = nullptr;
    cudaGetSymbolAddress((void**)&qkv_ptr, g_qkv);
    cudaGetSymbolAddress((void**)&att_ptr, g_att);

    // 1) qkv = x @ W_qkv + b_qkv    [8192, 2304]
    {
        dim3 grid(QKVN / 128, MROWS / 128);   // (18, 64)
        gemm_tf32_bias<<<grid, 256>>>(x, W_qkv, b_qkv, qkv_ptr,
                                      MROWS, QKVN, DMOD);
    }
    // 2) causal flash attention     [8192, 768]
    {
        int smem_bytes = (int)sizeof(AttnSmem);
        cudaFuncSetAttribute(attn_tf32_kernel,
                             cudaFuncAttributeMaxDynamicSharedMemorySize,
                             smem_bytes);
        dim3 grid(TLEN / 128, NHEAD, BSZ);    // (16, 12, 4)
        attn_tf32_kernel<<<grid, 256, smem_bytes>>>(qkv_ptr, att_ptr);
    }
    // 3) out = att @ W_o + b_o      [8192, 768]
    {
        dim3 grid(DMOD / 128, MROWS / 128);   // (6, 64)
        gemm_tf32_bias<<<grid, 256>>>(att_ptr, W_o, b_o, out,
                                      MROWS, DMOD, DMOD);
    }
}

// round 7
// speedup vs baseline: 2.3977x; 1.3473x over previous
#include <cuda_runtime.h>
#include <mma.h>
#include <cstddef>

using namespace nvcuda;

// Problem constants (fixed by the reference: B=4, T=2048, D=768, H=12)
#define BSZ   4
#define TLEN  2048
#define DMOD  768
#define NHEAD 12
#define HDIM  64
#define MROWS (BSZ * TLEN)       // 8192
#define QKVN  (3 * DMOD)         // 2304

// Scratch (no cudaMalloc allowed)
__device__ float g_qkv[(size_t)MROWS * QKVN];
__device__ float g_att[(size_t)MROWS * DMOD];

__device__ __forceinline__ float to_tf32(float x) {
    float r;
    asm("cvt.rna.tf32.f32 %0, %1;" : "=f"(r) : "f"(x));
    return r;
}

// mma.sync m16n8k8 tf32: D = A*B + D (documented fragment layout)
__device__ __forceinline__ void mma_tf32(float c[4], const unsigned a[4],
                                         unsigned b0, unsigned b1) {
    asm("mma.sync.aligned.m16n8k8.row.col.f32.tf32.tf32.f32 "
        "{%0,%1,%2,%3}, {%4,%5,%6,%7}, {%8,%9}, {%0,%1,%2,%3};"
        : "+f"(c[0]), "+f"(c[1]), "+f"(c[2]), "+f"(c[3])
        : "r"(a[0]), "r"(a[1]), "r"(a[2]), "r"(a[3]), "r"(b0), "r"(b1));
}

// ---------------------------------------------------------------------------
// TF32 wmma GEMM + bias, double-buffered smem pipeline.
// BM=BN=128, BK=32, 256 threads (8 warps), warp tile 64x32.
// One __syncthreads per K-step; next tile prefetched into regs during mma.
// ---------------------------------------------------------------------------
#define GA_ST 36
#define GB_ST 136

struct GemmSmem {
    float As[2][128][GA_ST];   // 36864 B
    float Bs[2][32][GB_ST];    // 34816 B
};                             // 71680 B

__global__ __launch_bounds__(256) void gemm_tf32_bias(
    const float* __restrict__ A, const float* __restrict__ B,
    const float* __restrict__ bias, float* __restrict__ C,
    int M, int N, int K)
{
    extern __shared__ char smem_raw[];
    GemmSmem& S = *reinterpret_cast<GemmSmem*>(smem_raw);

    const int tid   = threadIdx.x;
    const int wid   = tid >> 5;
    const int warpM = wid >> 2;
    const int warpN = wid & 3;
    const int bm    = blockIdx.y;
    const int bn    = blockIdx.x;

    wmma::fragment<wmma::accumulator, 16, 16, 8, float> c[4][2];

    // bias init via broadcast tile in Bs[0]
    for (int f = tid; f < 16 * 32; f += 256) {
        int r = f >> 5, c4 = f & 31;
        *(float4*)&S.Bs[0][r][c4 * 4] = *(const float4*)(bias + bn * 128 + c4 * 4);
    }
    __syncthreads();
#pragma unroll
    for (int i = 0; i < 4; i++)
#pragma unroll
        for (int j = 0; j < 2; j++)
            wmma::load_matrix_sync(c[i][j], &S.Bs[0][0][warpN * 32 + j * 16],
                                   GB_ST, wmma::mem_row_major);
    __syncthreads();

    const float* Ab = A + (size_t)bm * 128 * K;
    const float* Bb = B + (size_t)bn * 128;

    const int ar  = tid >> 3;          // 0..31 base, f>>3 overall
    const int nit = K / 32;

    float4 pa[4], pb[4];
    // prologue: load tile 0
#pragma unroll
    for (int i = 0; i < 4; i++) {
        int f = i * 256 + tid;
        int r = f >> 3, c4 = f & 7;
        float4 av = *(const float4*)(Ab + (size_t)r * K + c4 * 4);
        av.x = to_tf32(av.x); av.y = to_tf32(av.y);
        av.z = to_tf32(av.z); av.w = to_tf32(av.w);
        pa[i] = av;
        int br = f >> 5, bc4 = f & 31;
        float4 bv = *(const float4*)(Bb + (size_t)br * N + bc4 * 4);
        bv.x = to_tf32(bv.x); bv.y = to_tf32(bv.y);
        bv.z = to_tf32(bv.z); bv.w = to_tf32(bv.w);
        pb[i] = bv;
    }
#pragma unroll
    for (int i = 0; i < 4; i++) {
        int f = i * 256 + tid;
        int r = f >> 3, c4 = f & 7;
        *(float4*)&S.As[0][r][c4 * 4] = pa[i];
        int br = f >> 5, bc4 = f & 31;
        *(float4*)&S.Bs[0][br][bc4 * 4] = pb[i];
    }
    __syncthreads();
    (void)ar;

    for (int it = 0; it < nit; it++) {
        const int buf = it & 1;
        // prefetch next tile into regs (overlaps with mma below)
        if (it + 1 < nit) {
            int k0 = (it + 1) * 32;
#pragma unroll
            for (int i = 0; i < 4; i++) {
                int f = i * 256 + tid;
                int r = f >> 3, c4 = f & 7;
                float4 av = *(const float4*)(Ab + (size_t)r * K + k0 + c4 * 4);
                av.x = to_tf32(av.x); av.y = to_tf32(av.y);
                av.z = to_tf32(av.z); av.w = to_tf32(av.w);
                pa[i] = av;
                int br = f >> 5, bc4 = f & 31;
                float4 bv = *(const float4*)(Bb + (size_t)(k0 + br) * N + bc4 * 4);
                bv.x = to_tf32(bv.x); bv.y = to_tf32(bv.y);
                bv.z = to_tf32(bv.z); bv.w = to_tf32(bv.w);
                pb[i] = bv;
            }
        }
        // mma on current buffer
#pragma unroll
        for (int ks = 0; ks < 4; ks++) {
            wmma::fragment<wmma::matrix_a, 16, 16, 8, wmma::precision::tf32,
                           wmma::row_major> a[4];
            wmma::fragment<wmma::matrix_b, 16, 16, 8, wmma::precision::tf32,
                           wmma::row_major> b[2];
#pragma unroll
            for (int i = 0; i < 4; i++)
                wmma::load_matrix_sync(a[i],
                    &S.As[buf][warpM * 64 + i * 16][ks * 8], GA_ST);
#pragma unroll
            for (int j = 0; j < 2; j++)
                wmma::load_matrix_sync(b[j],
                    &S.Bs[buf][ks * 8][warpN * 32 + j * 16], GB_ST);
#pragma unroll
            for (int i = 0; i < 4; i++)
#pragma unroll
                for (int j = 0; j < 2; j++)
                    wmma::mma_sync(c[i][j], a[i], b[j], c[i][j]);
        }
        // store prefetched tile into the other buffer
        if (it + 1 < nit) {
#pragma unroll
            for (int i = 0; i < 4; i++) {
                int f = i * 256 + tid;
                int r = f >> 3, c4 = f & 7;
                *(float4*)&S.As[buf ^ 1][r][c4 * 4] = pa[i];
                int br = f >> 5, bc4 = f & 31;
                *(float4*)&S.Bs[buf ^ 1][br][bc4 * 4] = pb[i];
            }
        }
        __syncthreads();
    }

#pragma unroll
    for (int i = 0; i < 4; i++)
#pragma unroll
        for (int j = 0; j < 2; j++) {
            size_t row = (size_t)(bm * 128 + warpM * 64 + i * 16);
            int    col = bn * 128 + warpN * 32 + j * 16;
            wmma::store_matrix_sync(C + row * N + col, c[i][j], N,
                                    wmma::mem_row_major);
        }
}

// ---------------------------------------------------------------------------
// Causal flash attention with PTX mma.sync m16n8k8 tf32.
// CTA: 128 queries x one head; 64-key blocks; 256 threads (8 warps).
// Warp w owns rows [w*16, w*16+16). Q preloaded as A-frags (regs).
// S accumulators, softmax stats and O accumulator all live in registers
// (documented mma fragment layout: c0/c1 -> row lane>>2, c2/c3 -> +8).
// Only P transits smem. Smem stride 72 floats => conflict-free frag loads.
// ---------------------------------------------------------------------------
#define AS 72

struct AttnSmem {
    float Ks[64][AS];     // 18432 B
    float Vs[64][AS];     // 18432 B
    float Ps[128][AS];    // 36864 B (also initial Q staging)
};                        // 73728 B

__global__ __launch_bounds__(256) void attn_mma_kernel(
    const float* __restrict__ qkv, float* __restrict__ att)
{
    extern __shared__ char smem_raw[];
    AttnSmem& S = *reinterpret_cast<AttnSmem*>(smem_raw);

    const int qb   = (TLEN / 128) - 1 - blockIdx.x;   // longest CTAs first
    const int h    = blockIdx.y;
    const int b    = blockIdx.z;
    const int tid  = threadIdx.x;
    const int wid  = tid >> 5;
    const int lane = tid & 31;
    const int g    = lane >> 2;         // 0..7
    const int tc   = lane & 3;          // 0..3
    const int r0   = wid * 16 + g;      // local rows r0, r0+8
    const int gq0  = qb * 128 + r0;
    const int gq1  = gq0 + 8;

    // ---- Stage Q (prescaled, tf32) into Ps
    {
        const float scale = 0.125f;
#pragma unroll
        for (int i = 0; i < 8; i++) {
            int f = i * 256 + tid;
            int r = f >> 4, c4 = f & 15;
            float4 v = *(const float4*)(qkv +
                ((size_t)(b * TLEN + qb * 128 + r)) * QKVN + h * HDIM + c4 * 4);
            v.x = to_tf32(v.x * scale); v.y = to_tf32(v.y * scale);
            v.z = to_tf32(v.z * scale); v.w = to_tf32(v.w * scale);
            *(float4*)&S.Ps[r][c4 * 4] = v;
        }
    }
    __syncthreads();

    // ---- Preload Q fragments
    unsigned qa[8][4];
#pragma unroll
    for (int kk = 0; kk < 8; kk++) {
        qa[kk][0] = __float_as_uint(S.Ps[r0    ][kk * 8 + tc]);
        qa[kk][1] = __float_as_uint(S.Ps[r0 + 8][kk * 8 + tc]);
        qa[kk][2] = __float_as_uint(S.Ps[r0    ][kk * 8 + tc + 4]);
        qa[kk][3] = __float_as_uint(S.Ps[r0 + 8][kk * 8 + tc + 4]);
    }

    float oacc[8][4];
#pragma unroll
    for (int n = 0; n < 8; n++)
#pragma unroll
        for (int j = 0; j < 4; j++) oacc[n][j] = 0.0f;
    float m0 = -1e30f, m1 = -1e30f, l0 = 0.0f, l1 = 0.0f;

    const int nblk = 2 * qb + 2;
    for (int kb = 0; kb < nblk; kb++) {
        const int j0 = kb * 64;
        __syncthreads();                 // prior PV reads of Ps/Vs done

        // ---- Stage K, V (tf32)
#pragma unroll
        for (int i = 0; i < 4; i++) {
            int f = i * 256 + tid;
            int r = f >> 4, c4 = f & 15;
            size_t base = ((size_t)(b * TLEN + j0 + r)) * QKVN + h * HDIM;
            float4 kv = *(const float4*)(qkv + base + DMOD + c4 * 4);
            kv.x = to_tf32(kv.x); kv.y = to_tf32(kv.y);
            kv.z = to_tf32(kv.z); kv.w = to_tf32(kv.w);
            *(float4*)&S.Ks[r][c4 * 4] = kv;
            float4 vv = *(const float4*)(qkv + base + 2 * DMOD + c4 * 4);
            vv.x = to_tf32(vv.x); vv.y = to_tf32(vv.y);
            vv.z = to_tf32(vv.z); vv.w = to_tf32(vv.w);
            *(float4*)&S.Vs[r][c4 * 4] = vv;
        }
        __syncthreads();

        // ---- S = Q K^T : 16 rows x 64 keys per warp, in registers
        float sacc[8][4];
#pragma unroll
        for (int n = 0; n < 8; n++)
#pragma unroll
            for (int j = 0; j < 4; j++) sacc[n][j] = 0.0f;

#pragma unroll
        for (int kk = 0; kk < 8; kk++) {
#pragma unroll
            for (int n = 0; n < 8; n++) {
                unsigned b0 = __float_as_uint(S.Ks[n * 8 + g][kk * 8 + tc]);
                unsigned b1 = __float_as_uint(S.Ks[n * 8 + g][kk * 8 + tc + 4]);
                mma_tf32(sacc[n], qa[kk], b0, b1);
            }
        }

        // ---- Causal mask (only diagonal-overlapping blocks)
        if (kb >= 2 * qb) {
#pragma unroll
            for (int n = 0; n < 8; n++) {
                int col = j0 + n * 8 + tc * 2;
                if (col     > gq0) sacc[n][0] = -1e30f;
                if (col + 1 > gq0) sacc[n][1] = -1e30f;
                if (col     > gq1) sacc[n][2] = -1e30f;
                if (col + 1 > gq1) sacc[n][3] = -1e30f;
            }
        }

        // ---- Online softmax in registers (rows r0 and r0+8)
        float mx0 = -1e30f, mx1 = -1e30f;
#pragma unroll
        for (int n = 0; n < 8; n++) {
            mx0 = fmaxf(mx0, fmaxf(sacc[n][0], sacc[n][1]));
            mx1 = fmaxf(mx1, fmaxf(sacc[n][2], sacc[n][3]));
        }
        mx0 = fmaxf(mx0, __shfl_xor_sync(0xffffffffu, mx0, 1));
        mx0 = fmaxf(mx0, __shfl_xor_sync(0xffffffffu, mx0, 2));
        mx1 = fmaxf(mx1, __shfl_xor_sync(0xffffffffu, mx1, 1));
        mx1 = fmaxf(mx1, __shfl_xor_sync(0xffffffffu, mx1, 2));
        float nm0 = fmaxf(m0, mx0), nm1 = fmaxf(m1, mx1);
        float corr0 = __expf(m0 - nm0), corr1 = __expf(m1 - nm1);
        m0 = nm0; m1 = nm1;

        float sum0 = 0.0f, sum1 = 0.0f;
#pragma unroll
        for (int n = 0; n < 8; n++) {
            float p00 = __expf(sacc[n][0] - m0);
            float p01 = __expf(sacc[n][1] - m0);
            float p10 = __expf(sacc[n][2] - m1);
            float p11 = __expf(sacc[n][3] - m1);
            sum0 += p00 + p01;
            sum1 += p10 + p11;
            float2 t0 = make_float2(to_tf32(p00), to_tf32(p01));
            float2 t1 = make_float2(to_tf32(p10), to_tf32(p11));
            *(float2*)&S.Ps[r0    ][n * 8 + tc * 2] = t0;
            *(float2*)&S.Ps[r0 + 8][n * 8 + tc * 2] = t1;
        }
        sum0 += __shfl_xor_sync(0xffffffffu, sum0, 1);
        sum0 += __shfl_xor_sync(0xffffffffu, sum0, 2);
        sum1 += __shfl_xor_sync(0xffffffffu, sum1, 1);
        sum1 += __shfl_xor_sync(0xffffffffu, sum1, 2);
        l0 = l0 * corr0 + sum0;
        l1 = l1 * corr1 + sum1;

        // rescale O in registers
#pragma unroll
        for (int n = 0; n < 8; n++) {
            oacc[n][0] *= corr0; oacc[n][1] *= corr0;
            oacc[n][2] *= corr1; oacc[n][3] *= corr1;
        }
        __syncthreads();                 // P visible to all lanes

        // ---- O += P V : 16 rows x 64 dims per warp, in registers
#pragma unroll
        for (int kk = 0; kk < 8; kk++) {
            unsigned pa[4];
            pa[0] = __float_as_uint(S.Ps[r0    ][kk * 8 + tc]);
            pa[1] = __float_as_uint(S.Ps[r0 + 8][kk * 8 + tc]);
            pa[2] = __float_as_uint(S.Ps[r0    ][kk * 8 + tc + 4]);
            pa[3] = __float_as_uint(S.Ps[r0 + 8][kk * 8 + tc + 4]);
#pragma unroll
            for (int n = 0; n < 8; n++) {
                unsigned b0 = __float_as_uint(S.Vs[kk * 8 + tc    ][n * 8 + g]);
                unsigned b1 = __float_as_uint(S.Vs[kk * 8 + tc + 4][n * 8 + g]);
                mma_tf32(oacc[n], pa, b0, b1);
            }
        }
    }

    // ---- Epilogue: normalize, write [B,T,H*hd]
    {
        float inv0 = 1.0f / l0, inv1 = 1.0f / l1;
        float* d0 = att + ((size_t)(b * TLEN + gq0)) * DMOD + h * HDIM;
        float* d1 = att + ((size_t)(b * TLEN + gq1)) * DMOD + h * HDIM;
#pragma unroll
        for (int n = 0; n < 8; n++) {
            float2 v0 = make_float2(oacc[n][0] * inv0, oacc[n][1] * inv0);
            float2 v1 = make_float2(oacc[n][2] * inv1, oacc[n][3] * inv1);
            *(float2*)(d0 + n * 8 + tc * 2) = v0;
            *(float2*)(d1 + n * 8 + tc * 2) = v1;
        }
    }
}

// ---------------------------------------------------------------------------
// Launch: QKV GEMM -> flash attention -> output GEMM.
// ---------------------------------------------------------------------------
extern "C" void kernel_launch(void* const* d_in, const int* in_sizes, int n_in,
                              void* d_out, int out_size)
{
    (void)in_sizes; (void)n_in; (void)out_size;
    const float* x     = (const float*)d_in[0];
    const float* W_qkv = (const float*)d_in[1];
    const float* b_qkv = (const float*)d_in[2];
    const float* W_o   = (const float*)d_in[3];
    const float* b_o   = (const float*)d_in[4];
    float* out = (float*)d_out;

    float* qkv_ptr = nullptr;
    float* att_ptr = nullptr;
    cudaGetSymbolAddress((void**)&qkv_ptr, g_qkv);
    cudaGetSymbolAddress((void**)&att_ptr, g_att);

    int gemm_smem = (int)sizeof(GemmSmem);
    cudaFuncSetAttribute(gemm_tf32_bias,
                         cudaFuncAttributeMaxDynamicSharedMemorySize, gemm_smem);
    int attn_smem = (int)sizeof(AttnSmem);
    cudaFuncSetAttribute(attn_mma_kernel,
                         cudaFuncAttributeMaxDynamicSharedMemorySize, attn_smem);

    // 1) qkv = x @ W_qkv + b_qkv    [8192, 2304]
    {
        dim3 grid(QKVN / 128, MROWS / 128);   // (18, 64)
        gemm_tf32_bias<<<grid, 256, gemm_smem>>>(x, W_qkv, b_qkv, qkv_ptr,
                                                 MROWS, QKVN, DMOD);
    }
    // 2) causal flash attention     [8192, 768]
    {
        dim3 grid(TLEN / 128, NHEAD, BSZ);    // (16, 12, 4)
        attn_mma_kernel<<<grid, 256, attn_smem>>>(qkv_ptr, att_ptr);
    }
    // 3) out = att @ W_o + b_o      [8192, 768]
    {
        dim3 grid(DMOD / 128, MROWS / 128);   // (6, 64)
        gemm_tf32_bias<<<grid, 256, gemm_smem>>>(att_ptr, W_o, b_o, out,
                                                 MROWS, DMOD, DMOD);
    }
}

// round 8
// speedup vs baseline: 4.5578x; 1.9009x over previous
#include <cuda_runtime.h>
#include <cstddef>
#include <cstdint>

// Problem constants (fixed by the reference: B=4, T=2048, D=768, H=12)
#define BSZ   4
#define TLEN  2048
#define DMOD  768
#define NHEAD 12
#define HDIM  64
#define MROWS (BSZ * TLEN)       // 8192
#define QKVN  (3 * DMOD)         // 2304

// Scratch (no cudaMalloc allowed)
__device__ float g_qkv[(size_t)MROWS * QKVN];     // tf32-rounded qkv
__device__ float g_att[(size_t)MROWS * DMOD];     // tf32-rounded attn out
__device__ float g_x[(size_t)MROWS * DMOD];       // tf32-rounded x
__device__ float g_wqkv[(size_t)DMOD * QKVN];     // tf32-rounded W_qkv
__device__ float g_wo[(size_t)DMOD * DMOD];       // tf32-rounded W_o

__device__ __forceinline__ float to_tf32(float x) {
    float r;
    asm("cvt.rna.tf32.f32 %0, %1;" : "=f"(r) : "f"(x));
    return r;
}

// mma.sync m16n8k8 tf32: D = A*B + D (documented fragment layout)
__device__ __forceinline__ void mma_tf32(float c[4], const unsigned a[4],
                                         unsigned b0, unsigned b1) {
    asm("mma.sync.aligned.m16n8k8.row.col.f32.tf32.tf32.f32 "
        "{%0,%1,%2,%3}, {%4,%5,%6,%7}, {%8,%9}, {%0,%1,%2,%3};"
        : "+f"(c[0]), "+f"(c[1]), "+f"(c[2]), "+f"(c[3])
        : "r"(a[0]), "r"(a[1]), "r"(a[2]), "r"(a[3]), "r"(b0), "r"(b1));
}

__device__ __forceinline__ void cp16(uint32_t s, const float* g) {
    asm volatile("cp.async.cg.shared.global [%0], [%1], 16;" :: "r"(s), "l"(g));
}
__device__ __forceinline__ void cp_commit() {
    asm volatile("cp.async.commit_group;");
}
template<int N> __device__ __forceinline__ void cp_wait() {
    asm volatile("cp.async.wait_group %0;" :: "n"(N));
}

// ---------------------------------------------------------------------------
// Pre-round fp32 -> tf32-in-fp32 (elementwise, float4)
// ---------------------------------------------------------------------------
__global__ void round_tf32_kernel(const float4* __restrict__ in,
                                  float4* __restrict__ out, int n4)
{
    int i = blockIdx.x * blockDim.x + threadIdx.x;
    int stride = gridDim.x * blockDim.x;
    for (; i < n4; i += stride) {
        float4 v = in[i];
        v.x = to_tf32(v.x); v.y = to_tf32(v.y);
        v.z = to_tf32(v.z); v.w = to_tf32(v.w);
        out[i] = v;
    }
}

// ---------------------------------------------------------------------------
// TF32 PTX-mma GEMM + bias, cp.async 3-stage pipeline.
// BM=BN=128, BK=32, 256 threads (8 warps), warp tile 64x32 (4m x 4n m16n8k8).
// Inputs must already be tf32-rounded. One __syncthreads per K-step.
// ---------------------------------------------------------------------------
#define GS    3
#define GA_ST 36     // A row stride (floats): (g*36+tc)%32 distinct -> no conflicts
#define GB_ST 136    // B row stride (floats): (tc*136+g)%32 distinct

struct GemmSmem {
    float As[GS][128][GA_ST];   // 55296 B
    float Bs[GS][32][GB_ST];    // 52224 B
};                              // 107520 B

__global__ __launch_bounds__(256, 2) void gemm_mma_bias(
    const float* __restrict__ A, const float* __restrict__ B,
    const float* __restrict__ bias, float* __restrict__ C,
    int M, int N, int K, int round_out)
{
    extern __shared__ char smem_raw[];
    GemmSmem& S = *reinterpret_cast<GemmSmem*>(smem_raw);

    const int tid   = threadIdx.x;
    const int wid   = tid >> 5, lane = tid & 31;
    const int g     = lane >> 2, tc = lane & 3;
    const int warpM = wid >> 2, warpN = wid & 3;
    const int bm    = blockIdx.y, bn = blockIdx.x;

    const float* Ab = A + (size_t)bm * 128 * K;
    const float* Bb = B + (size_t)bn * 128;

    const uint32_t sbase  = (uint32_t)__cvta_generic_to_shared(smem_raw);
    const uint32_t BOFF   = (uint32_t)(GS * 128 * GA_ST * 4);

    const int a_r = tid >> 3, a_c = tid & 7;    // A: 128x32 = 1024 chunks
    const int b_r = tid >> 5, b_c = tid & 31;   // B: 32x128 = 1024 chunks

    float acc[4][4][4];
#pragma unroll
    for (int mt = 0; mt < 4; mt++)
#pragma unroll
        for (int nt = 0; nt < 4; nt++)
#pragma unroll
            for (int j = 0; j < 4; j++) acc[mt][nt][j] = 0.0f;

    // bias preload (per-lane columns)
    float bias0[4], bias1[4];
#pragma unroll
    for (int nt = 0; nt < 4; nt++) {
        int col = bn * 128 + warpN * 32 + nt * 8 + tc * 2;
        bias0[nt] = bias[col];
        bias1[nt] = bias[col + 1];
    }

    const int nit = K / 32;

#define GEMM_ISSUE(stage)                                                     \
    {                                                                         \
        int _buf = (stage) % GS; int _k0 = (stage) * 32;                      \
        _Pragma("unroll")                                                     \
        for (int i = 0; i < 4; i++) {                                         \
            int ar = i * 32 + a_r;                                            \
            cp16(sbase + (uint32_t)(((_buf * 128 + ar) * GA_ST + a_c * 4) * 4),\
                 Ab + (size_t)ar * K + _k0 + a_c * 4);                        \
            int br = i * 8 + b_r;                                             \
            cp16(sbase + BOFF + (uint32_t)(((_buf * 32 + br) * GB_ST + b_c * 4) * 4),\
                 Bb + (size_t)(_k0 + br) * N + b_c * 4);                      \
        }                                                                     \
        cp_commit();                                                          \
    }

    GEMM_ISSUE(0);
    GEMM_ISSUE(1);

    for (int it = 0; it < nit; it++) {
        if (it + 1 < nit) cp_wait<1>(); else cp_wait<0>();
        __syncthreads();
        if (it + 2 < nit) GEMM_ISSUE(it + 2);

        const int buf = it % GS;
#pragma unroll
        for (int ks = 0; ks < 4; ks++) {
            unsigned af[4][4], bf[4][2];
#pragma unroll
            for (int mt = 0; mt < 4; mt++) {
                int m0 = warpM * 64 + mt * 16;
                af[mt][0] = __float_as_uint(S.As[buf][m0 + g    ][ks * 8 + tc]);
                af[mt][1] = __float_as_uint(S.As[buf][m0 + g + 8][ks * 8 + tc]);
                af[mt][2] = __float_as_uint(S.As[buf][m0 + g    ][ks * 8 + tc + 4]);
                af[mt][3] = __float_as_uint(S.As[buf][m0 + g + 8][ks * 8 + tc + 4]);
            }
#pragma unroll
            for (int nt = 0; nt < 4; nt++) {
                int n0 = warpN * 32 + nt * 8;
                bf[nt][0] = __float_as_uint(S.Bs[buf][ks * 8 + tc    ][n0 + g]);
                bf[nt][1] = __float_as_uint(S.Bs[buf][ks * 8 + tc + 4][n0 + g]);
            }
#pragma unroll
            for (int mt = 0; mt < 4; mt++)
#pragma unroll
                for (int nt = 0; nt < 4; nt++)
                    mma_tf32(acc[mt][nt], af[mt], bf[nt][0], bf[nt][1]);
        }
    }

    // Epilogue
    float* Cb = C + (size_t)bm * 128 * N + bn * 128;
#pragma unroll
    for (int mt = 0; mt < 4; mt++) {
#pragma unroll
        for (int nt = 0; nt < 4; nt++) {
            int r0 = warpM * 64 + mt * 16 + g;
            int c0 = warpN * 32 + nt * 8 + tc * 2;
            float2 v0 = make_float2(acc[mt][nt][0] + bias0[nt],
                                    acc[mt][nt][1] + bias1[nt]);
            float2 v1 = make_float2(acc[mt][nt][2] + bias0[nt],
                                    acc[mt][nt][3] + bias1[nt]);
            if (round_out) {
                v0.x = to_tf32(v0.x); v0.y = to_tf32(v0.y);
                v1.x = to_tf32(v1.x); v1.y = to_tf32(v1.y);
            }
            *(float2*)(Cb + (size_t)r0 * N + c0)       = v0;
            *(float2*)(Cb + (size_t)(r0 + 8) * N + c0) = v1;
        }
    }
}

// ---------------------------------------------------------------------------
// Causal flash attention, PTX mma m16n8k8 tf32.
// qkv is pre-rounded to tf32 -> K/V staged raw via cp.async (double buffer).
// P exchange is warp-private -> __syncwarp instead of CTA barrier.
// One __syncthreads per key block.
// ---------------------------------------------------------------------------
#define AS 72

struct AttnSmem {
    float Ks[2][64][AS];   // 36864 B
    float Vs[2][64][AS];   // 36864 B
    float Ps[128][AS];     // 36864 B (also Q staging)
};                         // 110592 B

__global__ __launch_bounds__(256) void attn_mma_kernel(
    const float* __restrict__ qkv, float* __restrict__ att)
{
    extern __shared__ char smem_raw[];
    AttnSmem& S = *reinterpret_cast<AttnSmem*>(smem_raw);

    const int qb   = (TLEN / 128) - 1 - blockIdx.x;   // longest CTAs first
    const int h    = blockIdx.y;
    const int b    = blockIdx.z;
    const int tid  = threadIdx.x;
    const int wid  = tid >> 5;
    const int lane = tid & 31;
    const int g    = lane >> 2;
    const int tc   = lane & 3;
    const int r0   = wid * 16 + g;
    const int gq0  = qb * 128 + r0;
    const int gq1  = gq0 + 8;

    const uint32_t sbase = (uint32_t)__cvta_generic_to_shared(smem_raw);
    const uint32_t VOFF  = (uint32_t)(2 * 64 * AS * 4);

    const int kv_r = tid >> 4, kv_c = tid & 15;

#define ATTN_ISSUE(j0, buf)                                                   \
    {                                                                         \
        _Pragma("unroll")                                                     \
        for (int i = 0; i < 4; i++) {                                         \
            int r = i * 16 + kv_r;                                            \
            const float* base = qkv +                                         \
                ((size_t)(b * TLEN + (j0) + r)) * QKVN + h * HDIM + kv_c * 4; \
            uint32_t soff = (uint32_t)((((buf) * 64 + r) * AS + kv_c * 4) * 4);\
            cp16(sbase + soff, base + DMOD);                                  \
            cp16(sbase + VOFF + soff, base + 2 * DMOD);                       \
        }                                                                     \
        cp_commit();                                                          \
    }

    // prologue: start K/V block 0 immediately
    ATTN_ISSUE(0, 0);

    // Stage Q raw into Ps (values already tf32)
#pragma unroll
    for (int i = 0; i < 8; i++) {
        int f = i * 256 + tid;
        int r = f >> 4, c4 = f & 15;
        float4 v = *(const float4*)(qkv +
            ((size_t)(b * TLEN + qb * 128 + r)) * QKVN + h * HDIM + c4 * 4);
        *(float4*)&S.Ps[r][c4 * 4] = v;
    }
    __syncthreads();

    // Preload Q fragments with exact 1/8 scale (power of two keeps tf32)
    unsigned qa[8][4];
#pragma unroll
    for (int kk = 0; kk < 8; kk++) {
        qa[kk][0] = __float_as_uint(0.125f * S.Ps[r0    ][kk * 8 + tc]);
        qa[kk][1] = __float_as_uint(0.125f * S.Ps[r0 + 8][kk * 8 + tc]);
        qa[kk][2] = __float_as_uint(0.125f * S.Ps[r0    ][kk * 8 + tc + 4]);
        qa[kk][3] = __float_as_uint(0.125f * S.Ps[r0 + 8][kk * 8 + tc + 4]);
    }

    float oacc[8][4];
#pragma unroll
    for (int n = 0; n < 8; n++)
#pragma unroll
        for (int j = 0; j < 4; j++) oacc[n][j] = 0.0f;
    float m0 = -1e30f, m1 = -1e30f, l0 = 0.0f, l1 = 0.0f;

    const int nblk = 2 * qb + 2;
    for (int kb = 0; kb < nblk; kb++) {
        const int buf = kb & 1;
        const int j0  = kb * 64;

        __syncthreads();               // all warps done with buf^1 (prev PV)
        if (kb + 1 < nblk) ATTN_ISSUE((kb + 1) * 64, buf ^ 1);
        if (kb + 1 < nblk) cp_wait<1>(); else cp_wait<0>();

        // ---- S = Q K^T (registers)
        float sacc[8][4];
#pragma unroll
        for (int n = 0; n < 8; n++)
#pragma unroll
            for (int j = 0; j < 4; j++) sacc[n][j] = 0.0f;

#pragma unroll
        for (int kk = 0; kk < 8; kk++) {
#pragma unroll
            for (int n = 0; n < 8; n++) {
                unsigned b0 = __float_as_uint(S.Ks[buf][n * 8 + g][kk * 8 + tc]);
                unsigned b1 = __float_as_uint(S.Ks[buf][n * 8 + g][kk * 8 + tc + 4]);
                mma_tf32(sacc[n], qa[kk], b0, b1);
            }
        }

        // ---- Causal mask (diagonal blocks only)
        if (kb >= 2 * qb) {
#pragma unroll
            for (int n = 0; n < 8; n++) {
                int col = j0 + n * 8 + tc * 2;
                if (col     > gq0) sacc[n][0] = -1e30f;
                if (col + 1 > gq0) sacc[n][1] = -1e30f;
                if (col     > gq1) sacc[n][2] = -1e30f;
                if (col + 1 > gq1) sacc[n][3] = -1e30f;
            }
        }

        // ---- Online softmax (registers; quad-pair shfl reductions)
        float mx0 = -1e30f, mx1 = -1e30f;
#pragma unroll
        for (int n = 0; n < 8; n++) {
            mx0 = fmaxf(mx0, fmaxf(sacc[n][0], sacc[n][1]));
            mx1 = fmaxf(mx1, fmaxf(sacc[n][2], sacc[n][3]));
        }
        mx0 = fmaxf(mx0, __shfl_xor_sync(0xffffffffu, mx0, 1));
        mx0 = fmaxf(mx0, __shfl_xor_sync(0xffffffffu, mx0, 2));
        mx1 = fmaxf(mx1, __shfl_xor_sync(0xffffffffu, mx1, 1));
        mx1 = fmaxf(mx1, __shfl_xor_sync(0xffffffffu, mx1, 2));
        float nm0 = fmaxf(m0, mx0), nm1 = fmaxf(m1, mx1);
        float corr0 = __expf(m0 - nm0), corr1 = __expf(m1 - nm1);
        m0 = nm0; m1 = nm1;

        float sum0 = 0.0f, sum1 = 0.0f;
#pragma unroll
        for (int n = 0; n < 8; n++) {
            float p00 = __expf(sacc[n][0] - m0);
            float p01 = __expf(sacc[n][1] - m0);
            float p10 = __expf(sacc[n][2] - m1);
            float p11 = __expf(sacc[n][3] - m1);
            sum0 += p00 + p01;
            sum1 += p10 + p11;
            float2 t0 = make_float2(to_tf32(p00), to_tf32(p01));
            float2 t1 = make_float2(to_tf32(p10), to_tf32(p11));
            *(float2*)&S.Ps[r0    ][n * 8 + tc * 2] = t0;
            *(float2*)&S.Ps[r0 + 8][n * 8 + tc * 2] = t1;
        }
        sum0 += __shfl_xor_sync(0xffffffffu, sum0, 1);
        sum0 += __shfl_xor_sync(0xffffffffu, sum0, 2);
        sum1 += __shfl_xor_sync(0xffffffffu, sum1, 1);
        sum1 += __shfl_xor_sync(0xffffffffu, sum1, 2);
        l0 = l0 * corr0 + sum0;
        l1 = l1 * corr1 + sum1;

#pragma unroll
        for (int n = 0; n < 8; n++) {
            oacc[n][0] *= corr0; oacc[n][1] *= corr0;
            oacc[n][2] *= corr1; oacc[n][3] *= corr1;
        }
        __syncwarp();                   // P tile is warp-private

        // ---- O += P V (registers)
#pragma unroll
        for (int kk = 0; kk < 8; kk++) {
            unsigned pa[4];
            pa[0] = __float_as_uint(S.Ps[r0    ][kk * 8 + tc]);
            pa[1] = __float_as_uint(S.Ps[r0 + 8][kk * 8 + tc]);
            pa[2] = __float_as_uint(S.Ps[r0    ][kk * 8 + tc + 4]);
            pa[3] = __float_as_uint(S.Ps[r0 + 8][kk * 8 + tc + 4]);
#pragma unroll
            for (int n = 0; n < 8; n++) {
                unsigned b0 = __float_as_uint(S.Vs[buf][kk * 8 + tc    ][n * 8 + g]);
                unsigned b1 = __float_as_uint(S.Vs[buf][kk * 8 + tc + 4][n * 8 + g]);
                mma_tf32(oacc[n], pa, b0, b1);
            }
        }
    }

    // ---- Epilogue: normalize, round to tf32 (feeds GEMM2), write out
    {
        float inv0 = 1.0f / l0, inv1 = 1.0f / l1;
        float* d0 = att + ((size_t)(b * TLEN + gq0)) * DMOD + h * HDIM;
        float* d1 = att + ((size_t)(b * TLEN + gq1)) * DMOD + h * HDIM;
#pragma unroll
        for (int n = 0; n < 8; n++) {
            float2 v0 = make_float2(to_tf32(oacc[n][0] * inv0),
                                    to_tf32(oacc[n][1] * inv0));
            float2 v1 = make_float2(to_tf32(oacc[n][2] * inv1),
                                    to_tf32(oacc[n][3] * inv1));
            *(float2*)(d0 + n * 8 + tc * 2) = v0;
            *(float2*)(d1 + n * 8 + tc * 2) = v1;
        }
    }
}

// ---------------------------------------------------------------------------
// Launch: preconvert -> QKV GEMM -> flash attention -> output GEMM.
// ---------------------------------------------------------------------------
extern "C" void kernel_launch(void* const* d_in, const int* in_sizes, int n_in,
                              void* d_out, int out_size)
{
    (void)in_sizes; (void)n_in; (void)out_size;
    const float* x     = (const float*)d_in[0];
    const float* W_qkv = (const float*)d_in[1];
    const float* b_qkv = (const float*)d_in[2];
    const float* W_o   = (const float*)d_in[3];
    const float* b_o   = (const float*)d_in[4];
    float* out = (float*)d_out;

    float *qkv_ptr, *att_ptr, *x_ptr, *wqkv_ptr, *wo_ptr;
    cudaGetSymbolAddress((void**)&qkv_ptr,  g_qkv);
    cudaGetSymbolAddress((void**)&att_ptr,  g_att);
    cudaGetSymbolAddress((void**)&x_ptr,    g_x);
    cudaGetSymbolAddress((void**)&wqkv_ptr, g_wqkv);
    cudaGetSymbolAddress((void**)&wo_ptr,   g_wo);

    int gemm_smem = (int)sizeof(GemmSmem);
    cudaFuncSetAttribute(gemm_mma_bias,
                         cudaFuncAttributeMaxDynamicSharedMemorySize, gemm_smem);
    int attn_smem = (int)sizeof(AttnSmem);
    cudaFuncSetAttribute(attn_mma_kernel,
                         cudaFuncAttributeMaxDynamicSharedMemorySize, attn_smem);

    // 0) pre-round inputs/weights to tf32
    round_tf32_kernel<<<1184, 256>>>((const float4*)x, (float4*)x_ptr,
                                     MROWS * DMOD / 4);
    round_tf32_kernel<<<592, 256>>>((const float4*)W_qkv, (float4*)wqkv_ptr,
                                    DMOD * QKVN / 4);
    round_tf32_kernel<<<296, 256>>>((const float4*)W_o, (float4*)wo_ptr,
                                    DMOD * DMOD / 4);

    // 1) qkv = x @ W_qkv + b_qkv   [8192, 2304], rounded to tf32
    {
        dim3 grid(QKVN / 128, MROWS / 128);   // (18, 64)
        gemm_mma_bias<<<grid, 256, gemm_smem>>>(x_ptr, wqkv_ptr, b_qkv, qkv_ptr,
                                                MROWS, QKVN, DMOD, 1);
    }
    // 2) causal flash attention    [8192, 768], rounded to tf32
    {
        dim3 grid(TLEN / 128, NHEAD, BSZ);    // (16, 12, 4)
        attn_mma_kernel<<<grid, 256, attn_smem>>>(qkv_ptr, att_ptr);
    }
    // 3) out = att @ W_o + b_o     [8192, 768], full fp32 out
    {
        dim3 grid(DMOD / 128, MROWS / 128);   // (6, 64)
        gemm_mma_bias<<<grid, 256, gemm_smem>>>(att_ptr, wo_ptr, b_o, out,
                                                MROWS, DMOD, DMOD, 0);
    }
}

// round 9
// speedup vs baseline: 4.8151x; 1.0565x over previous
#include <cuda_runtime.h>
#include <cstddef>
#include <cstdint>

// Problem constants (fixed by the reference: B=4, T=2048, D=768, H=12)
#define BSZ   4
#define TLEN  2048
#define DMOD  768
#define NHEAD 12
#define HDIM  64
#define MROWS (BSZ * TLEN)       // 8192
#define QKVN  (3 * DMOD)         // 2304
#define K8    (DMOD / 8)         // 96 k-tiles (both GEMMs have K=768)

// Scratch (no cudaMalloc allowed)
__device__ float g_qkv[(size_t)MROWS * QKVN];     // tf32-rounded qkv (row-major)
__device__ float g_att[(size_t)MROWS * DMOD];     // attn out (row-major, tf32)
__device__ float g_aperm[(size_t)MROWS * DMOD];   // fragment-packed A operand
__device__ float g_wqkv[(size_t)DMOD * QKVN];     // fragment-packed W_qkv
__device__ float g_wo[(size_t)DMOD * DMOD];       // fragment-packed W_o

__device__ __forceinline__ float to_tf32(float x) {
    float r;
    asm("cvt.rna.tf32.f32 %0, %1;" : "=f"(r) : "f"(x));
    return r;
}

__device__ __forceinline__ void mma_tf32(float c[4], const unsigned a[4],
                                         unsigned b0, unsigned b1) {
    asm("mma.sync.aligned.m16n8k8.row.col.f32.tf32.tf32.f32 "
        "{%0,%1,%2,%3}, {%4,%5,%6,%7}, {%8,%9}, {%0,%1,%2,%3};"
        : "+f"(c[0]), "+f"(c[1]), "+f"(c[2]), "+f"(c[3])
        : "r"(a[0]), "r"(a[1]), "r"(a[2]), "r"(a[3]), "r"(b0), "r"(b1));
}

__device__ __forceinline__ void cp16(uint32_t s, const float* g) {
    asm volatile("cp.async.cg.shared.global [%0], [%1], 16;" :: "r"(s), "l"(g));
}
__device__ __forceinline__ void cp_commit() {
    asm volatile("cp.async.commit_group;");
}
template<int N> __device__ __forceinline__ void cp_wait() {
    asm volatile("cp.async.wait_group %0;" :: "n"(N));
}

// ---------------------------------------------------------------------------
// Permute+round A (M x 768 row-major) -> fragment-packed A_perm.
// A_perm chunk index = (m_tile * 96 + k_tile) * 32 + lane; chunk (lane g,tc) =
// { A[mt*16+g][kt*8+tc], A[g+8][tc], A[g][tc+4], A[g+8][tc+4] } (tf32).
// Block: 64x64 region via smem. M fixed 8192, K fixed 768.
// ---------------------------------------------------------------------------
__global__ __launch_bounds__(256) void perm_a_kernel(
    const float* __restrict__ in, float4* __restrict__ out)
{
    __shared__ float Ts[64][68];
    const int bmr = blockIdx.y;          // 0..127 (row block of 64)
    const int bkr = blockIdx.x;          // 0..11  (col block of 64)
    const int tid = threadIdx.x;

#pragma unroll
    for (int i = 0; i < 4; i++) {
        int f = i * 256 + tid;           // 1024 float4
        int r = f >> 4, c4 = f & 15;
        *(float4*)&Ts[r][c4 * 4] =
            *(const float4*)(in + (size_t)(bmr * 64 + r) * DMOD + bkr * 64 + c4 * 4);
    }
    __syncthreads();

#pragma unroll
    for (int i = 0; i < 4; i++) {
        int f    = i * 256 + tid;
        int tile = f >> 5;               // 0..31
        int mt   = tile >> 3, kt = tile & 7;
        int l    = f & 31;
        int g    = l >> 2, tc = l & 3;
        float4 v;
        v.x = to_tf32(Ts[mt * 16 + g    ][kt * 8 + tc]);
        v.y = to_tf32(Ts[mt * 16 + g + 8][kt * 8 + tc]);
        v.z = to_tf32(Ts[mt * 16 + g    ][kt * 8 + tc + 4]);
        v.w = to_tf32(Ts[mt * 16 + g + 8][kt * 8 + tc + 4]);
        out[((size_t)(bmr * 4 + mt) * K8 + (bkr * 8 + kt)) * 32 + l] = v;
    }
}

// ---------------------------------------------------------------------------
// Permute+round B (768 x N row-major) -> fragment-packed B_perm.
// B_perm chunk index = (n_pair * 96 + k_tile) * 32 + lane; chunk (lane g,tc) =
// { B[kt*8+tc][np*16+g], B[tc+4][g], B[tc][8+g], B[tc+4][8+g] } (tf32)
// i.e. two n-tiles' b-fragments per 16B.
// ---------------------------------------------------------------------------
__global__ __launch_bounds__(256) void perm_b_kernel(
    const float* __restrict__ in, float4* __restrict__ out, int N)
{
    __shared__ float Ts[64][68];
    const int bkr = blockIdx.y;          // 0..11 (k block of 64)
    const int bnr = blockIdx.x;          // N/64  (n block of 64)
    const int tid = threadIdx.x;

#pragma unroll
    for (int i = 0; i < 4; i++) {
        int f = i * 256 + tid;
        int r = f >> 4, c4 = f & 15;
        *(float4*)&Ts[r][c4 * 4] =
            *(const float4*)(in + (size_t)(bkr * 64 + r) * N + bnr * 64 + c4 * 4);
    }
    __syncthreads();

#pragma unroll
    for (int i = 0; i < 4; i++) {
        int f    = i * 256 + tid;
        int tile = f >> 5;               // 0..31
        int kt   = tile >> 2, np = tile & 3;
        int l    = f & 31;
        int g    = l >> 2, tc = l & 3;
        float4 v;
        v.x = to_tf32(Ts[kt * 8 + tc    ][np * 16 + g]);
        v.y = to_tf32(Ts[kt * 8 + tc + 4][np * 16 + g]);
        v.z = to_tf32(Ts[kt * 8 + tc    ][np * 16 + 8 + g]);
        v.w = to_tf32(Ts[kt * 8 + tc + 4][np * 16 + 8 + g]);
        out[((size_t)(bnr * 4 + np) * K8 + (bkr * 8 + kt)) * 32 + l] = v;
    }
}

// ---------------------------------------------------------------------------
// TF32 GEMM on fragment-packed operands + bias.
// BM=BN=128, BK=32, 256 threads (8 warps), warp tile 64x32.
// Hot loop: 6 LDS.128 per 16 mmas, 2-deep fragment pipeline.
// cp.async 3-stage gmem->smem pipeline, one __syncthreads per K-step.
// C written row-major (+bias, optional tf32 round).
// ---------------------------------------------------------------------------
#define GS 3

__global__ __launch_bounds__(256, 2) void gemm_mma_perm(
    const float* __restrict__ A, const float* __restrict__ B,
    const float* __restrict__ bias, float* __restrict__ C,
    int N, int round_out)
{
    extern __shared__ char smem_raw[];

    const int tid   = threadIdx.x;
    const int wid   = tid >> 5, lane = tid & 31;
    const int g     = lane >> 2, tc = lane & 3;
    const int warpM = wid >> 2, warpN = wid & 3;
    const int bm    = blockIdx.y, bn = blockIdx.x;

    const float4* A4 = (const float4*)A;
    const float4* B4 = (const float4*)B;

    const uint32_t sbase = (uint32_t)__cvta_generic_to_shared(smem_raw);
    const uint32_t BOFF  = (uint32_t)(GS * 8 * 4 * 32 * 16);   // 49152 B

    float acc[4][4][4];
#pragma unroll
    for (int mt = 0; mt < 4; mt++)
#pragma unroll
        for (int nt = 0; nt < 4; nt++)
#pragma unroll
            for (int j = 0; j < 4; j++) acc[mt][nt][j] = 0.0f;

    float bias0[4], bias1[4];
#pragma unroll
    for (int nt = 0; nt < 4; nt++) {
        int col = bn * 128 + warpN * 32 + nt * 8 + tc * 2;
        bias0[nt] = bias[col];
        bias1[nt] = bias[col + 1];
    }

    const int nit = K8 / 4;    // 24

#define GEMM_ISSUE(stage)                                                      \
    {                                                                          \
        int _buf = (stage) % GS; int _k4 = (stage) * 4;                        \
        _Pragma("unroll")                                                      \
        for (int i = 0; i < 4; i++) {                                          \
            int f = i * 256 + tid;                                             \
            int mt = f >> 7, kt = (f >> 5) & 3, l = f & 31;                    \
            cp16(sbase + (uint32_t)((((_buf * 8 + mt) * 4 + kt) * 32 + l) * 16),\
                 (const float*)(A4 + ((size_t)(bm * 8 + mt) * K8 + _k4 + kt) * 32 + l));\
            cp16(sbase + BOFF + (uint32_t)((((_buf * 8 + mt) * 4 + kt) * 32 + l) * 16),\
                 (const float*)(B4 + ((size_t)(bn * 8 + mt) * K8 + _k4 + kt) * 32 + l));\
        }                                                                      \
        cp_commit();                                                           \
    }

    GEMM_ISSUE(0);
    GEMM_ISSUE(1);

    for (int it = 0; it < nit; it++) {
        if (it + 1 < nit) cp_wait<1>(); else cp_wait<0>();
        __syncthreads();
        if (it + 2 < nit) GEMM_ISSUE(it + 2);

        const int buf = it % GS;
        const float4* Ab4 = (const float4*)smem_raw + (size_t)buf * 8 * 4 * 32;
        const float4* Bb4 = (const float4*)(smem_raw + BOFF) + (size_t)buf * 8 * 4 * 32;

        float4 afv[2][4], bfv[2][2];
#pragma unroll
        for (int mt = 0; mt < 4; mt++)
            afv[0][mt] = Ab4[((warpM * 4 + mt) * 4 + 0) * 32 + lane];
#pragma unroll
        for (int p = 0; p < 2; p++)
            bfv[0][p] = Bb4[((warpN * 2 + p) * 4 + 0) * 32 + lane];

#pragma unroll
        for (int ks = 0; ks < 4; ks++) {
            const int cur = ks & 1;
            if (ks < 3) {
#pragma unroll
                for (int mt = 0; mt < 4; mt++)
                    afv[cur ^ 1][mt] = Ab4[((warpM * 4 + mt) * 4 + ks + 1) * 32 + lane];
#pragma unroll
                for (int p = 0; p < 2; p++)
                    bfv[cur ^ 1][p] = Bb4[((warpN * 2 + p) * 4 + ks + 1) * 32 + lane];
            }
#pragma unroll
            for (int mt = 0; mt < 4; mt++) {
                unsigned a[4];
                a[0] = __float_as_uint(afv[cur][mt].x);
                a[1] = __float_as_uint(afv[cur][mt].y);
                a[2] = __float_as_uint(afv[cur][mt].z);
                a[3] = __float_as_uint(afv[cur][mt].w);
#pragma unroll
                for (int nt = 0; nt < 4; nt++) {
                    const float4& bp = bfv[cur][nt >> 1];
                    unsigned b0 = (nt & 1) ? __float_as_uint(bp.z)
                                           : __float_as_uint(bp.x);
                    unsigned b1 = (nt & 1) ? __float_as_uint(bp.w)
                                           : __float_as_uint(bp.y);
                    mma_tf32(acc[mt][nt], a, b0, b1);
                }
            }
        }
    }

    // Epilogue: bias, optional tf32 round, row-major store
    float* Cb = C + (size_t)bm * 128 * N + bn * 128;
#pragma unroll
    for (int mt = 0; mt < 4; mt++) {
#pragma unroll
        for (int nt = 0; nt < 4; nt++) {
            int r0 = warpM * 64 + mt * 16 + g;
            int c0 = warpN * 32 + nt * 8 + tc * 2;
            float2 v0 = make_float2(acc[mt][nt][0] + bias0[nt],
                                    acc[mt][nt][1] + bias1[nt]);
            float2 v1 = make_float2(acc[mt][nt][2] + bias0[nt],
                                    acc[mt][nt][3] + bias1[nt]);
            if (round_out) {
                v0.x = to_tf32(v0.x); v0.y = to_tf32(v0.y);
                v1.x = to_tf32(v1.x); v1.y = to_tf32(v1.y);
            }
            *(float2*)(Cb + (size_t)r0 * N + c0)       = v0;
            *(float2*)(Cb + (size_t)(r0 + 8) * N + c0) = v1;
        }
    }
}

// ---------------------------------------------------------------------------
// Causal flash attention, PTX mma m16n8k8 tf32 (unchanged structure from R8,
// plus __launch_bounds__(256,2) so two CTAs share an SM).
// ---------------------------------------------------------------------------
#define AS 72

struct AttnSmem {
    float Ks[2][64][AS];   // 36864 B
    float Vs[2][64][AS];   // 36864 B
    float Ps[128][AS];     // 36864 B (also Q staging)
};                         // 110592 B

__global__ __launch_bounds__(256, 2) void attn_mma_kernel(
    const float* __restrict__ qkv, float* __restrict__ att)
{
    extern __shared__ char smem_raw[];
    AttnSmem& S = *reinterpret_cast<AttnSmem*>(smem_raw);

    const int qb   = (TLEN / 128) - 1 - blockIdx.x;   // longest CTAs first
    const int h    = blockIdx.y;
    const int b    = blockIdx.z;
    const int tid  = threadIdx.x;
    const int wid  = tid >> 5;
    const int lane = tid & 31;
    const int g    = lane >> 2;
    const int tc   = lane & 3;
    const int r0   = wid * 16 + g;
    const int gq0  = qb * 128 + r0;
    const int gq1  = gq0 + 8;

    const uint32_t sbase = (uint32_t)__cvta_generic_to_shared(smem_raw);
    const uint32_t VOFF  = (uint32_t)(2 * 64 * AS * 4);

    const int kv_r = tid >> 4, kv_c = tid & 15;

#define ATTN_ISSUE(j0, buf)                                                   \
    {                                                                         \
        _Pragma("unroll")                                                     \
        for (int i = 0; i < 4; i++) {                                         \
            int r = i * 16 + kv_r;                                            \
            const float* base = qkv +                                         \
                ((size_t)(b * TLEN + (j0) + r)) * QKVN + h * HDIM + kv_c * 4; \
            uint32_t soff = (uint32_t)((((buf) * 64 + r) * AS + kv_c * 4) * 4);\
            cp16(sbase + soff, base + DMOD);                                  \
            cp16(sbase + VOFF + soff, base + 2 * DMOD);                       \
        }                                                                     \
        cp_commit();                                                          \
    }

    ATTN_ISSUE(0, 0);

    // Stage Q raw into Ps (values already tf32)
#pragma unroll
    for (int i = 0; i < 8; i++) {
        int f = i * 256 + tid;
        int r = f >> 4, c4 = f & 15;
        float4 v = *(const float4*)(qkv +
            ((size_t)(b * TLEN + qb * 128 + r)) * QKVN + h * HDIM + c4 * 4);
        *(float4*)&S.Ps[r][c4 * 4] = v;
    }
    __syncthreads();

    // Preload Q fragments with exact 1/8 scale (power of two keeps tf32)
    unsigned qa[8][4];
#pragma unroll
    for (int kk = 0; kk < 8; kk++) {
        qa[kk][0] = __float_as_uint(0.125f * S.Ps[r0    ][kk * 8 + tc]);
        qa[kk][1] = __float_as_uint(0.125f * S.Ps[r0 + 8][kk * 8 + tc]);
        qa[kk][2] = __float_as_uint(0.125f * S.Ps[r0    ][kk * 8 + tc + 4]);
        qa[kk][3] = __float_as_uint(0.125f * S.Ps[r0 + 8][kk * 8 + tc + 4]);
    }

    float oacc[8][4];
#pragma unroll
    for (int n = 0; n < 8; n++)
#pragma unroll
        for (int j = 0; j < 4; j++) oacc[n][j] = 0.0f;
    float m0 = -1e30f, m1 = -1e30f, l0 = 0.0f, l1 = 0.0f;

    const int nblk = 2 * qb + 2;
    for (int kb = 0; kb < nblk; kb++) {
        const int buf = kb & 1;
        const int j0  = kb * 64;

        __syncthreads();
        if (kb + 1 < nblk) ATTN_ISSUE((kb + 1) * 64, buf ^ 1);
        if (kb + 1 < nblk) cp_wait<1>(); else cp_wait<0>();

        // ---- S = Q K^T (registers)
        float sacc[8][4];
#pragma unroll
        for (int n = 0; n < 8; n++)
#pragma unroll
            for (int j = 0; j < 4; j++) sacc[n][j] = 0.0f;

#pragma unroll
        for (int kk = 0; kk < 8; kk++) {
#pragma unroll
            for (int n = 0; n < 8; n++) {
                unsigned b0 = __float_as_uint(S.Ks[buf][n * 8 + g][kk * 8 + tc]);
                unsigned b1 = __float_as_uint(S.Ks[buf][n * 8 + g][kk * 8 + tc + 4]);
                mma_tf32(sacc[n], qa[kk], b0, b1);
            }
        }

        // ---- Causal mask (diagonal blocks only)
        if (kb >= 2 * qb) {
#pragma unroll
            for (int n = 0; n < 8; n++) {
                int col = j0 + n * 8 + tc * 2;
                if (col     > gq0) sacc[n][0] = -1e30f;
                if (col + 1 > gq0) sacc[n][1] = -1e30f;
                if (col     > gq1) sacc[n][2] = -1e30f;
                if (col + 1 > gq1) sacc[n][3] = -1e30f;
            }
        }

        // ---- Online softmax (registers; quad-pair shfl reductions)
        float mx0 = -1e30f, mx1 = -1e30f;
#pragma unroll
        for (int n = 0; n < 8; n++) {
            mx0 = fmaxf(mx0, fmaxf(sacc[n][0], sacc[n][1]));
            mx1 = fmaxf(mx1, fmaxf(sacc[n][2], sacc[n][3]));
        }
        mx0 = fmaxf(mx0, __shfl_xor_sync(0xffffffffu, mx0, 1));
        mx0 = fmaxf(mx0, __shfl_xor_sync(0xffffffffu, mx0, 2));
        mx1 = fmaxf(mx1, __shfl_xor_sync(0xffffffffu, mx1, 1));
        mx1 = fmaxf(mx1, __shfl_xor_sync(0xffffffffu, mx1, 2));
        float nm0 = fmaxf(m0, mx0), nm1 = fmaxf(m1, mx1);
        float corr0 = __expf(m0 - nm0), corr1 = __expf(m1 - nm1);
        m0 = nm0; m1 = nm1;

        float sum0 = 0.0f, sum1 = 0.0f;
#pragma unroll
        for (int n = 0; n < 8; n++) {
            float p00 = __expf(sacc[n][0] - m0);
            float p01 = __expf(sacc[n][1] - m0);
            float p10 = __expf(sacc[n][2] - m1);
            float p11 = __expf(sacc[n][3] - m1);
            sum0 += p00 + p01;
            sum1 += p10 + p11;
            float2 t0 = make_float2(to_tf32(p00), to_tf32(p01));
            float2 t1 = make_float2(to_tf32(p10), to_tf32(p11));
            *(float2*)&S.Ps[r0    ][n * 8 + tc * 2] = t0;
            *(float2*)&S.Ps[r0 + 8][n * 8 + tc * 2] = t1;
        }
        sum0 += __shfl_xor_sync(0xffffffffu, sum0, 1);
        sum0 += __shfl_xor_sync(0xffffffffu, sum0, 2);
        sum1 += __shfl_xor_sync(0xffffffffu, sum1, 1);
        sum1 += __shfl_xor_sync(0xffffffffu, sum1, 2);
        l0 = l0 * corr0 + sum0;
        l1 = l1 * corr1 + sum1;

#pragma unroll
        for (int n = 0; n < 8; n++) {
            oacc[n][0] *= corr0; oacc[n][1] *= corr0;
            oacc[n][2] *= corr1; oacc[n][3] *= corr1;
        }
        __syncwarp();                   // P tile is warp-private

        // ---- O += P V (registers)
#pragma unroll
        for (int kk = 0; kk < 8; kk++) {
            unsigned pa[4];
            pa[0] = __float_as_uint(S.Ps[r0    ][kk * 8 + tc]);
            pa[1] = __float_as_uint(S.Ps[r0 + 8][kk * 8 + tc]);
            pa[2] = __float_as_uint(S.Ps[r0    ][kk * 8 + tc + 4]);
            pa[3] = __float_as_uint(S.Ps[r0 + 8][kk * 8 + tc + 4]);
#pragma unroll
            for (int n = 0; n < 8; n++) {
                unsigned b0 = __float_as_uint(S.Vs[buf][kk * 8 + tc    ][n * 8 + g]);
                unsigned b1 = __float_as_uint(S.Vs[buf][kk * 8 + tc + 4][n * 8 + g]);
                mma_tf32(oacc[n], pa, b0, b1);
            }
        }
    }

    // ---- Epilogue: normalize, round to tf32 (feeds perm+GEMM2), write out
    {
        float inv0 = 1.0f / l0, inv1 = 1.0f / l1;
        float* d0 = att + ((size_t)(b * TLEN + gq0)) * DMOD + h * HDIM;
        float* d1 = att + ((size_t)(b * TLEN + gq1)) * DMOD + h * HDIM;
#pragma unroll
        for (int n = 0; n < 8; n++) {
            float2 v0 = make_float2(to_tf32(oacc[n][0] * inv0),
                                    to_tf32(oacc[n][1] * inv0));
            float2 v1 = make_float2(to_tf32(oacc[n][2] * inv1),
                                    to_tf32(oacc[n][3] * inv1));
            *(float2*)(d0 + n * 8 + tc * 2) = v0;
            *(float2*)(d1 + n * 8 + tc * 2) = v1;
        }
    }
}

// ---------------------------------------------------------------------------
// Launch: permute -> QKV GEMM -> attention -> permute -> output GEMM.
// ---------------------------------------------------------------------------
extern "C" void kernel_launch(void* const* d_in, const int* in_sizes, int n_in,
                              void* d_out, int out_size)
{
    (void)in_sizes; (void)n_in; (void)out_size;
    const float* x     = (const float*)d_in[0];
    const float* W_qkv = (const float*)d_in[1];
    const float* b_qkv = (const float*)d_in[2];
    const float* W_o   = (const float*)d_in[3];
    const float* b_o   = (const float*)d_in[4];
    float* out = (float*)d_out;

    float *qkv_ptr, *att_ptr, *ap_ptr, *wqkv_ptr, *wo_ptr;
    cudaGetSymbolAddress((void**)&qkv_ptr,  g_qkv);
    cudaGetSymbolAddress((void**)&att_ptr,  g_att);
    cudaGetSymbolAddress((void**)&ap_ptr,   g_aperm);
    cudaGetSymbolAddress((void**)&wqkv_ptr, g_wqkv);
    cudaGetSymbolAddress((void**)&wo_ptr,   g_wo);

    int gemm_smem = GS * 2 * 8 * 4 * 32 * 16;     // 98304 B
    cudaFuncSetAttribute(gemm_mma_perm,
                         cudaFuncAttributeMaxDynamicSharedMemorySize, gemm_smem);
    int attn_smem = (int)sizeof(AttnSmem);
    cudaFuncSetAttribute(attn_mma_kernel,
                         cudaFuncAttributeMaxDynamicSharedMemorySize, attn_smem);

    // 0) pack operands (x -> A_perm, W -> B_perm), rounding to tf32
    {
        dim3 ga(DMOD / 64, MROWS / 64);           // (12, 128)
        perm_a_kernel<<<ga, 256>>>(x, (float4*)ap_ptr);
        dim3 g1(QKVN / 64, DMOD / 64);            // (36, 12)
        perm_b_kernel<<<g1, 256>>>(W_qkv, (float4*)wqkv_ptr, QKVN);
        dim3 g2(DMOD / 64, DMOD / 64);            // (12, 12)
        perm_b_kernel<<<g2, 256>>>(W_o, (float4*)wo_ptr, DMOD);
    }
    // 1) qkv = x @ W_qkv + b_qkv   [8192, 2304], rounded to tf32
    {
        dim3 grid(QKVN / 128, MROWS / 128);       // (18, 64)
        gemm_mma_perm<<<grid, 256, gemm_smem>>>(ap_ptr, wqkv_ptr, b_qkv,
                                                qkv_ptr, QKVN, 1);
    }
    // 2) causal flash attention    [8192, 768], rounded to tf32
    {
        dim3 grid(TLEN / 128, NHEAD, BSZ);        // (16, 12, 4)
        attn_mma_kernel<<<grid, 256, attn_smem>>>(qkv_ptr, att_ptr);
    }
    // 2b) pack attention output as A operand for GEMM2
    {
        dim3 ga(DMOD / 64, MROWS / 64);           // (12, 128)
        perm_a_kernel<<<ga, 256>>>(att_ptr, (float4*)ap_ptr);
    }
    // 3) out = att @ W_o + b_o     [8192, 768], full fp32 out
    {
        dim3 grid(DMOD / 128, MROWS / 128);       // (6, 64)
        gemm_mma_perm<<<grid, 256, gemm_smem>>>(ap_ptr, wo_ptr, b_o,
                                                out, DMOD, 0);
    }
}

// round 12
// speedup vs baseline: 8.9123x; 1.8509x over previous
#include <cuda_runtime.h>
#include <cuda_fp16.h>
#include <cstddef>
#include <cstdint>

// Problem constants (fixed by the reference: B=4, T=2048, D=768, H=12)
#define BSZ   4
#define TLEN  2048
#define DMOD  768
#define NHEAD 12
#define HDIM  64
#define MROWS (BSZ * TLEN)       // 8192
#define QKVN  (3 * DMOD)         // 2304
#define K16   (DMOD / 16)        // 48 k16-tiles (both GEMMs have K=768)

// Scratch (no cudaMalloc allowed)
__device__ __half g_qkvh[(size_t)MROWS * QKVN];      // QKV row-major half
__device__ __half g_vt[(size_t)BSZ * NHEAD * HDIM * TLEN];  // V transposed [b,h,d,t]
__device__ __half g_xa[(size_t)MROWS * DMOD];        // x, A-fragment-packed
__device__ __half g_ao[(size_t)MROWS * DMOD];        // attn out, A-fragment-packed
__device__ __half g_wqkvh[(size_t)DMOD * QKVN];      // W_qkv, B-fragment-packed
__device__ __half g_woh[(size_t)DMOD * DMOD];        // W_o, B-fragment-packed

__device__ __forceinline__ unsigned h2u(__half2 h) {
    return *reinterpret_cast<unsigned*>(&h);
}

// mma.sync m16n8k16 fp16 inputs, fp32 accumulate (documented fragment layout)
__device__ __forceinline__ void mma_f16(float c[4], const unsigned a[4],
                                        unsigned b01, unsigned b23) {
    asm("mma.sync.aligned.m16n8k16.row.col.f32.f16.f16.f32 "
        "{%0,%1,%2,%3}, {%4,%5,%6,%7}, {%8,%9}, {%0,%1,%2,%3};"
        : "+f"(c[0]), "+f"(c[1]), "+f"(c[2]), "+f"(c[3])
        : "r"(a[0]), "r"(a[1]), "r"(a[2]), "r"(a[3]), "r"(b01), "r"(b23));
}

__device__ __forceinline__ void cp16(uint32_t s, const void* g) {
    asm volatile("cp.async.cg.shared.global [%0], [%1], 16;" :: "r"(s), "l"(g));
}
__device__ __forceinline__ void cp_commit() {
    asm volatile("cp.async.commit_group;");
}
template<int N> __device__ __forceinline__ void cp_wait() {
    asm volatile("cp.async.wait_group %0;" :: "n"(N));
}

// ---------------------------------------------------------------------------
// Pack A (M x 768 fp32 row-major) -> fp16 A-fragment chunks.
// ---------------------------------------------------------------------------
__global__ __launch_bounds__(256) void perm_a_half(
    const float* __restrict__ in, float4* __restrict__ out)
{
    __shared__ float Ts[64][68];
    const int bmr = blockIdx.y;          // 0..127 (64-row block)
    const int bkr = blockIdx.x;          // 0..11  (64-col block)
    const int tid = threadIdx.x;

#pragma unroll
    for (int i = 0; i < 4; i++) {
        int f = i * 256 + tid;
        int r = f >> 4, c4 = f & 15;
        *(float4*)&Ts[r][c4 * 4] =
            *(const float4*)(in + (size_t)(bmr * 64 + r) * DMOD + bkr * 64 + c4 * 4);
    }
    __syncthreads();

#pragma unroll
    for (int i = 0; i < 2; i++) {
        int f    = i * 256 + tid;        // 0..511
        int tile = f >> 5;               // 0..15
        int mt   = tile >> 2, kt = tile & 3;
        int l    = f & 31, g = l >> 2, tc = l & 3;
        int r = mt * 16, c = kt * 16;
        float4 v;
        v.x = __uint_as_float(h2u(__floats2half2_rn(Ts[r+g  ][c+2*tc  ], Ts[r+g  ][c+2*tc+1])));
        v.y = __uint_as_float(h2u(__floats2half2_rn(Ts[r+g+8][c+2*tc  ], Ts[r+g+8][c+2*tc+1])));
        v.z = __uint_as_float(h2u(__floats2half2_rn(Ts[r+g  ][c+2*tc+8], Ts[r+g  ][c+2*tc+9])));
        v.w = __uint_as_float(h2u(__floats2half2_rn(Ts[r+g+8][c+2*tc+8], Ts[r+g+8][c+2*tc+9])));
        out[((size_t)(bmr * 4 + mt) * K16 + (bkr * 4 + kt)) * 32 + l] = v;
    }
}

// ---------------------------------------------------------------------------
// Pack B (768 x N fp32 row-major) -> fp16 B-fragment chunks.
// ---------------------------------------------------------------------------
__global__ __launch_bounds__(256) void perm_b_half(
    const float* __restrict__ in, float4* __restrict__ out, int N)
{
    __shared__ float Ts[64][68];
    const int bkr = blockIdx.y;          // 0..11 (64-k block)
    const int bnr = blockIdx.x;          // N/64
    const int tid = threadIdx.x;

#pragma unroll
    for (int i = 0; i < 4; i++) {
        int f = i * 256 + tid;
        int r = f >> 4, c4 = f & 15;
        *(float4*)&Ts[r][c4 * 4] =
            *(const float4*)(in + (size_t)(bkr * 64 + r) * N + bnr * 64 + c4 * 4);
    }
    __syncthreads();

#pragma unroll
    for (int i = 0; i < 2; i++) {
        int f    = i * 256 + tid;
        int tile = f >> 5;
        int np   = tile >> 2, kt = tile & 3;
        int l    = f & 31, g = l >> 2, tc = l & 3;
        int r = kt * 16, c = np * 16;
        float4 v;
        v.x = __uint_as_float(h2u(__floats2half2_rn(Ts[r+2*tc  ][c+g  ], Ts[r+2*tc+1][c+g  ])));
        v.y = __uint_as_float(h2u(__floats2half2_rn(Ts[r+2*tc+8][c+g  ], Ts[r+2*tc+9][c+g  ])));
        v.z = __uint_as_float(h2u(__floats2half2_rn(Ts[r+2*tc  ][c+8+g], Ts[r+2*tc+1][c+8+g])));
        v.w = __uint_as_float(h2u(__floats2half2_rn(Ts[r+2*tc+8][c+8+g], Ts[r+2*tc+9][c+8+g])));
        out[((size_t)(bnr * 4 + np) * K16 + (bkr * 4 + kt)) * 32 + l] = v;
    }
}

// ---------------------------------------------------------------------------
// V transpose: g_qkvh V region (row-major, col offset 1536) -> g_vt[b,h,d,t].
// 64x64 half tiles via smem. Simple and fully verifiable.
// ---------------------------------------------------------------------------
__global__ __launch_bounds__(256) void vtrans_kernel(
    const __half* __restrict__ qkvh, __half* __restrict__ vt)
{
    __shared__ __half Ts[64][72];
    const int bt  = blockIdx.x;          // 0..31 (64-row t block)
    const int h   = blockIdx.y;          // 0..11
    const int b   = blockIdx.z;          // 0..3
    const int tid = threadIdx.x;

    // load 64 t-rows x 64 d-cols (512 float4, 2/thread)
#pragma unroll
    for (int i = 0; i < 2; i++) {
        int f = i * 256 + tid;
        int r = f >> 3, c8 = f & 7;
        *(float4*)&Ts[r][c8 * 8] = *(const float4*)(qkvh +
            (size_t)(b * TLEN + bt * 64 + r) * QKVN + 2 * DMOD + h * HDIM + c8 * 8);
    }
    __syncthreads();

    // store 64 d-rows x 64 t-cols
#pragma unroll
    for (int i = 0; i < 2; i++) {
        int f = i * 256 + tid;
        int d = f >> 3, t8 = f & 7;
        __half tmp[8];
#pragma unroll
        for (int j = 0; j < 8; j++) tmp[j] = Ts[t8 * 8 + j][d];
        *(float4*)(vt + ((size_t)(b * NHEAD + h) * HDIM + d) * TLEN
                      + bt * 64 + t8 * 8) = *(float4*)tmp;
    }
}

// ---------------------------------------------------------------------------
// fp16 GEMM on fragment-packed operands + bias (fp32 accumulate).
// BM=BN=128, K-slab 64 (4 k16-tiles), 256 threads, warp tile 64x32.
// mode 0: fp32 C out. mode 1: half2 row-major out into g_qkvh (uniform path).
// ---------------------------------------------------------------------------
#define GS 3

__global__ __launch_bounds__(256, 2) void gemm_f16(
    const float4* __restrict__ A4, const float4* __restrict__ B4,
    const float* __restrict__ bias, float* __restrict__ C,
    int N, int mode)
{
    extern __shared__ char smem_raw[];

    const int tid   = threadIdx.x;
    const int wid   = tid >> 5, lane = tid & 31;
    const int g     = lane >> 2, tc = lane & 3;
    const int warpM = wid >> 2, warpN = wid & 3;
    const int bm    = blockIdx.y, bn = blockIdx.x;

    const uint32_t sbase = (uint32_t)__cvta_generic_to_shared(smem_raw);
    const uint32_t BOFF  = (uint32_t)(GS * 8 * 4 * 32 * 16);   // 49152 B

    float acc[4][4][4];
#pragma unroll
    for (int mt = 0; mt < 4; mt++)
#pragma unroll
        for (int nt = 0; nt < 4; nt++)
#pragma unroll
            for (int j = 0; j < 4; j++) acc[mt][nt][j] = 0.0f;

    float bias0[4], bias1[4];
#pragma unroll
    for (int nt = 0; nt < 4; nt++) {
        int col = bn * 128 + warpN * 32 + nt * 8 + tc * 2;
        bias0[nt] = bias[col];
        bias1[nt] = bias[col + 1];
    }

    const int nit = K16 / 4;   // 12

#define GEMM_ISSUE(stage)                                                      \
    {                                                                          \
        int _buf = (stage) % GS; int _k4 = (stage) * 4;                        \
        _Pragma("unroll")                                                      \
        for (int i = 0; i < 4; i++) {                                          \
            int f = i * 256 + tid;                                             \
            int mt = f >> 7, kt = (f >> 5) & 3, l = f & 31;                    \
            cp16(sbase + (uint32_t)((((_buf * 8 + mt) * 4 + kt) * 32 + l) * 16),\
                 A4 + ((size_t)(bm * 8 + mt) * K16 + _k4 + kt) * 32 + l);      \
            cp16(sbase + BOFF + (uint32_t)((((_buf * 8 + mt) * 4 + kt) * 32 + l) * 16),\
                 B4 + ((size_t)(bn * 8 + mt) * K16 + _k4 + kt) * 32 + l);      \
        }                                                                      \
        cp_commit();                                                           \
    }

    GEMM_ISSUE(0);
    GEMM_ISSUE(1);

    for (int it = 0; it < nit; it++) {
        if (it + 1 < nit) cp_wait<1>(); else cp_wait<0>();
        __syncthreads();
        if (it + 2 < nit) GEMM_ISSUE(it + 2);

        const int buf = it % GS;
        const float4* Ab4 = (const float4*)smem_raw + (size_t)buf * 8 * 4 * 32;
        const float4* Bb4 = (const float4*)(smem_raw + BOFF) + (size_t)buf * 8 * 4 * 32;

        float4 afv[2][4], bfv[2][2];
#pragma unroll
        for (int mt = 0; mt < 4; mt++)
            afv[0][mt] = Ab4[((warpM * 4 + mt) * 4 + 0) * 32 + lane];
#pragma unroll
        for (int p = 0; p < 2; p++)
            bfv[0][p] = Bb4[((warpN * 2 + p) * 4 + 0) * 32 + lane];

#pragma unroll
        for (int ks = 0; ks < 4; ks++) {
            const int cur = ks & 1;
            if (ks < 3) {
#pragma unroll
                for (int mt = 0; mt < 4; mt++)
                    afv[cur ^ 1][mt] = Ab4[((warpM * 4 + mt) * 4 + ks + 1) * 32 + lane];
#pragma unroll
                for (int p = 0; p < 2; p++)
                    bfv[cur ^ 1][p] = Bb4[((warpN * 2 + p) * 4 + ks + 1) * 32 + lane];
            }
#pragma unroll
            for (int mt = 0; mt < 4; mt++) {
                unsigned a[4];
                a[0] = __float_as_uint(afv[cur][mt].x);
                a[1] = __float_as_uint(afv[cur][mt].y);
                a[2] = __float_as_uint(afv[cur][mt].z);
                a[3] = __float_as_uint(afv[cur][mt].w);
#pragma unroll
                for (int nt = 0; nt < 4; nt++) {
                    const float4& bp = bfv[cur][nt >> 1];
                    unsigned b01 = (nt & 1) ? __float_as_uint(bp.z)
                                            : __float_as_uint(bp.x);
                    unsigned b23 = (nt & 1) ? __float_as_uint(bp.w)
                                            : __float_as_uint(bp.y);
                    mma_f16(acc[mt][nt], a, b01, b23);
                }
            }
        }
    }

    // ---- Epilogue
    if (mode == 0) {
        float* Cb = C + (size_t)bm * 128 * N + bn * 128;
#pragma unroll
        for (int mt = 0; mt < 4; mt++)
#pragma unroll
            for (int nt = 0; nt < 4; nt++) {
                int r0 = warpM * 64 + mt * 16 + g;
                int c0 = warpN * 32 + nt * 8 + tc * 2;
                float2 v0 = make_float2(acc[mt][nt][0] + bias0[nt],
                                        acc[mt][nt][1] + bias1[nt]);
                float2 v1 = make_float2(acc[mt][nt][2] + bias0[nt],
                                        acc[mt][nt][3] + bias1[nt]);
                *(float2*)(Cb + (size_t)r0 * N + c0)       = v0;
                *(float2*)(Cb + (size_t)(r0 + 8) * N + c0) = v1;
            }
    } else {
        // half2 row-major into g_qkvh (uniform for Q, K and V columns)
#pragma unroll
        for (int mt = 0; mt < 4; mt++)
#pragma unroll
            for (int nt = 0; nt < 4; nt++) {
                int r0 = bm * 128 + warpM * 64 + mt * 16 + g;
                int c0 = bn * 128 + warpN * 32 + nt * 8 + tc * 2;
                __half2 v0 = __floats2half2_rn(acc[mt][nt][0] + bias0[nt],
                                               acc[mt][nt][1] + bias1[nt]);
                __half2 v1 = __floats2half2_rn(acc[mt][nt][2] + bias0[nt],
                                               acc[mt][nt][3] + bias1[nt]);
                *(__half2*)&g_qkvh[(size_t)r0 * QKVN + c0]       = v0;
                *(__half2*)&g_qkvh[(size_t)(r0 + 8) * QKVN + c0] = v1;
            }
    }
}

// ---------------------------------------------------------------------------
// Causal flash attention, fp16 mma m16n8k16, fp32 softmax/accumulators.
// CTA: 128 queries x one head; 64-key blocks; 256 threads (8 warps).
// K row-major half, V transposed half (both cp.async double-buffered).
// Output written directly as GEMM-A fragment-packed half (g_ao).
// ---------------------------------------------------------------------------
#define AS2 72    // halves per smem row (144 B): conflict-free frag loads

struct AttnSmem {
    __half Ks[2][64][AS2];   // 18432 B
    __half Vs[2][64][AS2];   // 18432 B (V transposed: [d][key])
    __half Ps[128][AS2];     // 18432 B (Q staging, then P)
};                           // 55296 B

__global__ __launch_bounds__(256, 2) void attn_f16_kernel(
    const __half* __restrict__ qkvh, const __half* __restrict__ vt,
    float4* __restrict__ outp)
{
    extern __shared__ char smem_raw[];
    AttnSmem& S = *reinterpret_cast<AttnSmem*>(smem_raw);

    const int qb   = (TLEN / 128) - 1 - blockIdx.x;   // longest CTAs first
    const int h    = blockIdx.y;
    const int b    = blockIdx.z;
    const int tid  = threadIdx.x;
    const int wid  = tid >> 5;
    const int lane = tid & 31;
    const int g    = lane >> 2;
    const int tc   = lane & 3;
    const int r0   = wid * 16 + g;
    const int gq0  = qb * 128 + r0;
    const int gq1  = gq0 + 8;

    const uint32_t sbase = (uint32_t)__cvta_generic_to_shared(smem_raw);
    const uint32_t VOFF  = (uint32_t)sizeof(S.Ks);
    const uint32_t POFF  = VOFF + (uint32_t)sizeof(S.Vs);

#define ATTN_ISSUE(j0, buf)                                                    \
    {                                                                          \
        _Pragma("unroll")                                                      \
        for (int i = 0; i < 4; i++) {                                          \
            int f = i * 256 + tid;                                             \
            int r = (f >> 3) & 63, c8 = f & 7;                                 \
            if (f < 512) {                                                     \
                cp16(sbase + (uint32_t)((((buf) * 64 + r) * AS2 + c8 * 8) * 2),\
                     qkvh + (size_t)(b * TLEN + (j0) + r) * QKVN + DMOD        \
                          + h * HDIM + c8 * 8);                                \
            } else {                                                           \
                cp16(sbase + VOFF + (uint32_t)((((buf) * 64 + r) * AS2 + c8 * 8) * 2),\
                     vt + ((size_t)(b * NHEAD + h) * HDIM + r) * TLEN          \
                        + (j0) + c8 * 8);                                      \
            }                                                                  \
        }                                                                      \
        cp_commit();                                                           \
    }

    // Q staging (same commit group as K/V block 0)
#pragma unroll
    for (int i = 0; i < 4; i++) {
        int f = i * 256 + tid;
        int r = f >> 3, c8 = f & 7;
        cp16(sbase + POFF + (uint32_t)((r * AS2 + c8 * 8) * 2),
             qkvh + (size_t)(b * TLEN + qb * 128 + r) * QKVN + h * HDIM + c8 * 8);
    }
    ATTN_ISSUE(0, 0);

    float oacc[8][4];
#pragma unroll
    for (int n = 0; n < 8; n++)
#pragma unroll
        for (int j = 0; j < 4; j++) oacc[n][j] = 0.0f;
    float m0 = -1e30f, m1 = -1e30f, l0 = 0.0f, l1 = 0.0f;

    const int nblk = 2 * qb + 2;     // >= 2 always

    // Prologue: prefetch block 1, wait for {Q, KV0}, preload Q fragments
    unsigned qa[4][4];
    {
        ATTN_ISSUE(64, 1);
        cp_wait<1>();
        __syncthreads();
        const __half2 sc = __float2half2_rn(0.125f);
#pragma unroll
        for (int kk = 0; kk < 4; kk++) {
            __half2 t0 = __hmul2(*(__half2*)&S.Ps[r0    ][kk * 16 + 2 * tc    ], sc);
            __half2 t1 = __hmul2(*(__half2*)&S.Ps[r0 + 8][kk * 16 + 2 * tc    ], sc);
            __half2 t2 = __hmul2(*(__half2*)&S.Ps[r0    ][kk * 16 + 2 * tc + 8], sc);
            __half2 t3 = __hmul2(*(__half2*)&S.Ps[r0 + 8][kk * 16 + 2 * tc + 8], sc);
            qa[kk][0] = h2u(t0); qa[kk][1] = h2u(t1);
            qa[kk][2] = h2u(t2); qa[kk][3] = h2u(t3);
        }
        __syncwarp();   // Q rows are warp-private; later P writes are same rows
    }

    for (int kb = 0; kb < nblk; kb++) {
        const int buf = kb & 1;
        const int j0  = kb * 64;

        if (kb > 0) {
            __syncthreads();               // all warps done with buf (prev use)
            if (kb + 1 < nblk) ATTN_ISSUE((kb + 1) * 64, buf ^ 1);
            if (kb + 1 < nblk) cp_wait<1>(); else cp_wait<0>();
            __syncthreads();               // staged data visible to all
        }

        // ---- S = Q K^T (fp32 acc in registers)
        float sacc[8][4];
#pragma unroll
        for (int n = 0; n < 8; n++)
#pragma unroll
            for (int j = 0; j < 4; j++) sacc[n][j] = 0.0f;

#pragma unroll
        for (int kk = 0; kk < 4; kk++) {
#pragma unroll
            for (int n = 0; n < 8; n++) {
                unsigned b01 = *(unsigned*)&S.Ks[buf][n * 8 + g][kk * 16 + 2 * tc];
                unsigned b23 = *(unsigned*)&S.Ks[buf][n * 8 + g][kk * 16 + 2 * tc + 8];
                mma_f16(sacc[n], qa[kk], b01, b23);
            }
        }

        // ---- Causal mask (diagonal blocks only)
        if (kb >= 2 * qb) {
#pragma unroll
            for (int n = 0; n < 8; n++) {
                int col = j0 + n * 8 + tc * 2;
                if (col     > gq0) sacc[n][0] = -1e30f;
                if (col + 1 > gq0) sacc[n][1] = -1e30f;
                if (col     > gq1) sacc[n][2] = -1e30f;
                if (col + 1 > gq1) sacc[n][3] = -1e30f;
            }
        }

        // ---- Online softmax (fp32, register stats)
        float mx0 = -1e30f, mx1 = -1e30f;
#pragma unroll
        for (int n = 0; n < 8; n++) {
            mx0 = fmaxf(mx0, fmaxf(sacc[n][0], sacc[n][1]));
            mx1 = fmaxf(mx1, fmaxf(sacc[n][2], sacc[n][3]));
        }
        mx0 = fmaxf(mx0, __shfl_xor_sync(0xffffffffu, mx0, 1));
        mx0 = fmaxf(mx0, __shfl_xor_sync(0xffffffffu, mx0, 2));
        mx1 = fmaxf(mx1, __shfl_xor_sync(0xffffffffu, mx1, 1));
        mx1 = fmaxf(mx1, __shfl_xor_sync(0xffffffffu, mx1, 2));
        float nm0 = fmaxf(m0, mx0), nm1 = fmaxf(m1, mx1);
        float corr0 = __expf(m0 - nm0), corr1 = __expf(m1 - nm1);
        m0 = nm0; m1 = nm1;

        float sum0 = 0.0f, sum1 = 0.0f;
#pragma unroll
        for (int n = 0; n < 8; n++) {
            float p00 = __expf(sacc[n][0] - m0);
            float p01 = __expf(sacc[n][1] - m0);
            float p10 = __expf(sacc[n][2] - m1);
            float p11 = __expf(sacc[n][3] - m1);
            sum0 += p00 + p01;
            sum1 += p10 + p11;
            *(__half2*)&S.Ps[r0    ][n * 8 + tc * 2] = __floats2half2_rn(p00, p01);
            *(__half2*)&S.Ps[r0 + 8][n * 8 + tc * 2] = __floats2half2_rn(p10, p11);
        }
        sum0 += __shfl_xor_sync(0xffffffffu, sum0, 1);
        sum0 += __shfl_xor_sync(0xffffffffu, sum0, 2);
        sum1 += __shfl_xor_sync(0xffffffffu, sum1, 1);
        sum1 += __shfl_xor_sync(0xffffffffu, sum1, 2);
        l0 = l0 * corr0 + sum0;
        l1 = l1 * corr1 + sum1;

#pragma unroll
        for (int n = 0; n < 8; n++) {
            oacc[n][0] *= corr0; oacc[n][1] *= corr0;
            oacc[n][2] *= corr1; oacc[n][3] *= corr1;
        }
        __syncwarp();                     // P tile is warp-private

        // ---- O += P V (V transposed in smem: Vs[d][key])
#pragma unroll
        for (int kk = 0; kk < 4; kk++) {
            unsigned pa[4];
            pa[0] = *(unsigned*)&S.Ps[r0    ][kk * 16 + 2 * tc];
            pa[1] = *(unsigned*)&S.Ps[r0 + 8][kk * 16 + 2 * tc];
            pa[2] = *(unsigned*)&S.Ps[r0    ][kk * 16 + 2 * tc + 8];
            pa[3] = *(unsigned*)&S.Ps[r0 + 8][kk * 16 + 2 * tc + 8];
#pragma unroll
            for (int n = 0; n < 8; n++) {
                unsigned b01 = *(unsigned*)&S.Vs[buf][n * 8 + g][kk * 16 + 2 * tc];
                unsigned b23 = *(unsigned*)&S.Vs[buf][n * 8 + g][kk * 16 + 2 * tc + 8];
                mma_f16(oacc[n], pa, b01, b23);
            }
        }
    }

    // ---- Epilogue: normalize, emit GEMM-A fragment-packed half chunks
    {
        float inv0 = 1.0f / l0, inv1 = 1.0f / l1;
        int mt_glob = b * 128 + qb * 8 + wid;       // 16-row tile index
#pragma unroll
        for (int kp = 0; kp < 4; kp++) {
            int n0 = 2 * kp, n1 = 2 * kp + 1;
            float4 v;
            v.x = __uint_as_float(h2u(__floats2half2_rn(oacc[n0][0] * inv0,
                                                        oacc[n0][1] * inv0)));
            v.y = __uint_as_float(h2u(__floats2half2_rn(oacc[n0][2] * inv1,
                                                        oacc[n0][3] * inv1)));
            v.z = __uint_as_float(h2u(__floats2half2_rn(oacc[n1][0] * inv0,
                                                        oacc[n1][1] * inv0)));
            v.w = __uint_as_float(h2u(__floats2half2_rn(oacc[n1][2] * inv1,
                                                        oacc[n1][3] * inv1)));
            int kt_glob = h * 4 + kp;
            outp[((size_t)mt_glob * K16 + kt_glob) * 32 + lane] = v;
        }
    }
}

// ---------------------------------------------------------------------------
// Launch: pack -> QKV GEMM -> V transpose -> attention -> output GEMM.
// ---------------------------------------------------------------------------
extern "C" void kernel_launch(void* const* d_in, const int* in_sizes, int n_in,
                              void* d_out, int out_size)
{
    (void)in_sizes; (void)n_in; (void)out_size;
    const float* x     = (const float*)d_in[0];
    const float* W_qkv = (const float*)d_in[1];
    const float* b_qkv = (const float*)d_in[2];
    const float* W_o   = (const float*)d_in[3];
    const float* b_o   = (const float*)d_in[4];
    float* out = (float*)d_out;

    void *qkvh_p, *vt_p, *xa_p, *ao_p, *wqkv_p, *wo_p;
    cudaGetSymbolAddress(&qkvh_p, g_qkvh);
    cudaGetSymbolAddress(&vt_p,   g_vt);
    cudaGetSymbolAddress(&xa_p,   g_xa);
    cudaGetSymbolAddress(&ao_p,   g_ao);
    cudaGetSymbolAddress(&wqkv_p, g_wqkvh);
    cudaGetSymbolAddress(&wo_p,   g_woh);

    int gemm_smem = GS * 2 * 8 * 4 * 32 * 16;     // 98304 B
    cudaFuncSetAttribute(gemm_f16,
                         cudaFuncAttributeMaxDynamicSharedMemorySize, gemm_smem);
    int attn_smem = (int)sizeof(AttnSmem);
    cudaFuncSetAttribute(attn_f16_kernel,
                         cudaFuncAttributeMaxDynamicSharedMemorySize, attn_smem);

    // 0) pack operands to fp16 fragment layouts
    {
        dim3 ga(DMOD / 64, MROWS / 64);           // (12, 128)
        perm_a_half<<<ga, 256>>>(x, (float4*)xa_p);
        dim3 g1(QKVN / 64, DMOD / 64);            // (36, 12)
        perm_b_half<<<g1, 256>>>(W_qkv, (float4*)wqkv_p, QKVN);
        dim3 g2(DMOD / 64, DMOD / 64);            // (12, 12)
        perm_b_half<<<g2, 256>>>(W_o, (float4*)wo_p, DMOD);
    }
    // 1) qkv = x @ W_qkv + b_qkv -> QKV half row-major
    {
        dim3 grid(QKVN / 128, MROWS / 128);       // (18, 64)
        gemm_f16<<<grid, 256, gemm_smem>>>((const float4*)xa_p,
                                           (const float4*)wqkv_p,
                                           b_qkv, nullptr, QKVN, 1);
    }
    // 1b) transpose V region -> g_vt[b,h,d,t]
    {
        dim3 gv(TLEN / 64, NHEAD, BSZ);           // (32, 12, 4)
        vtrans_kernel<<<gv, 256>>>((const __half*)qkvh_p, (__half*)vt_p);
    }
    // 2) causal flash attention -> packed A operand for GEMM2
    {
        dim3 grid(TLEN / 128, NHEAD, BSZ);        // (16, 12, 4)
        attn_f16_kernel<<<grid, 256, attn_smem>>>((const __half*)qkvh_p,
                                                  (const __half*)vt_p,
                                                  (float4*)ao_p);
    }
    // 3) out = att @ W_o + b_o (fp32 out)
    {
        dim3 grid(DMOD / 128, MROWS / 128);       // (6, 64)
        gemm_f16<<<grid, 256, gemm_smem>>>((const float4*)ao_p,
                                           (const float4*)wo_p,
                                           b_o, out, DMOD, 0);
    }
}

// round 17
// speedup vs baseline: 9.3151x; 1.0452x over previous
#include <cuda_runtime.h>
#include <cuda_fp16.h>
#include <cstddef>
#include <cstdint>

// Problem constants (fixed by the reference: B=4, T=2048, D=768, H=12)
#define BSZ   4
#define TLEN  2048
#define DMOD  768
#define NHEAD 12
#define HDIM  64
#define MROWS (BSZ * TLEN)       // 8192
#define QKVN  (3 * DMOD)         // 2304
#define K16   (DMOD / 16)        // 48 k16-tiles (both GEMMs have K=768)

// Scratch (no cudaMalloc allowed)
__device__ __half g_qkvh[(size_t)MROWS * QKVN];      // QKV row-major half
__device__ __half g_vt[(size_t)BSZ * NHEAD * HDIM * TLEN];  // V transposed [b,h,d,t]
__device__ __half g_xa[(size_t)MROWS * DMOD];        // x, A-fragment-packed
__device__ __half g_ao[(size_t)MROWS * DMOD];        // attn out, A-fragment-packed
__device__ __half g_wqkvh[(size_t)DMOD * QKVN];      // W_qkv, B-fragment-packed
__device__ __half g_woh[(size_t)DMOD * DMOD];        // W_o, B-fragment-packed

__device__ __forceinline__ unsigned h2u(__half2 h) {
    return *reinterpret_cast<unsigned*>(&h);
}

// mma.sync m16n8k16 fp16 inputs, fp32 accumulate (documented fragment layout)
__device__ __forceinline__ void mma_f16(float c[4], const unsigned a[4],
                                        unsigned b01, unsigned b23) {
    asm("mma.sync.aligned.m16n8k16.row.col.f32.f16.f16.f32 "
        "{%0,%1,%2,%3}, {%4,%5,%6,%7}, {%8,%9}, {%0,%1,%2,%3};"
        : "+f"(c[0]), "+f"(c[1]), "+f"(c[2]), "+f"(c[3])
        : "r"(a[0]), "r"(a[1]), "r"(a[2]), "r"(a[3]), "r"(b01), "r"(b23));
}

// ldmatrix x4: four 8x8 b16 matrices; lane l supplies the row address of
// matrix l>>3, row l&7. Output reg j: lane(g,tc) holds matrix j row g,
// halves 2tc, 2tc+1.
__device__ __forceinline__ void ldsm4(unsigned& r0, unsigned& r1,
                                      unsigned& r2, unsigned& r3, uint32_t a) {
    asm volatile("ldmatrix.sync.aligned.m8n8.x4.shared.b16 {%0,%1,%2,%3}, [%4];"
                 : "=r"(r0), "=r"(r1), "=r"(r2), "=r"(r3) : "r"(a));
}

__device__ __forceinline__ void cp16(uint32_t s, const void* g) {
    asm volatile("cp.async.cg.shared.global [%0], [%1], 16;" :: "r"(s), "l"(g));
}
__device__ __forceinline__ void cp_commit() {
    asm volatile("cp.async.commit_group;");
}
template<int N> __device__ __forceinline__ void cp_wait() {
    asm volatile("cp.async.wait_group %0;" :: "n"(N));
}

// ---------------------------------------------------------------------------
// Pack A (M x 768 fp32 row-major) -> fp16 A-fragment chunks.
// ---------------------------------------------------------------------------
__global__ __launch_bounds__(256) void perm_a_half(
    const float* __restrict__ in, float4* __restrict__ out)
{
    __shared__ float Ts[64][68];
    const int bmr = blockIdx.y;          // 0..127 (64-row block)
    const int bkr = blockIdx.x;          // 0..11  (64-col block)
    const int tid = threadIdx.x;

#pragma unroll
    for (int i = 0; i < 4; i++) {
        int f = i * 256 + tid;
        int r = f >> 4, c4 = f & 15;
        *(float4*)&Ts[r][c4 * 4] =
            *(const float4*)(in + (size_t)(bmr * 64 + r) * DMOD + bkr * 64 + c4 * 4);
    }
    __syncthreads();

#pragma unroll
    for (int i = 0; i < 2; i++) {
        int f    = i * 256 + tid;        // 0..511
        int tile = f >> 5;               // 0..15
        int mt   = tile >> 2, kt = tile & 3;
        int l    = f & 31, g = l >> 2, tc = l & 3;
        int r = mt * 16, c = kt * 16;
        float4 v;
        v.x = __uint_as_float(h2u(__floats2half2_rn(Ts[r+g  ][c+2*tc  ], Ts[r+g  ][c+2*tc+1])));
        v.y = __uint_as_float(h2u(__floats2half2_rn(Ts[r+g+8][c+2*tc  ], Ts[r+g+8][c+2*tc+1])));
        v.z = __uint_as_float(h2u(__floats2half2_rn(Ts[r+g  ][c+2*tc+8], Ts[r+g  ][c+2*tc+9])));
        v.w = __uint_as_float(h2u(__floats2half2_rn(Ts[r+g+8][c+2*tc+8], Ts[r+g+8][c+2*tc+9])));
        out[((size_t)(bmr * 4 + mt) * K16 + (bkr * 4 + kt)) * 32 + l] = v;
    }
}

// ---------------------------------------------------------------------------
// Pack B (768 x N fp32 row-major) -> fp16 B-fragment chunks.
// ---------------------------------------------------------------------------
__global__ __launch_bounds__(256) void perm_b_half(
    const float* __restrict__ in, float4* __restrict__ out, int N)
{
    __shared__ float Ts[64][68];
    const int bkr = blockIdx.y;          // 0..11 (64-k block)
    const int bnr = blockIdx.x;          // N/64
    const int tid = threadIdx.x;

#pragma unroll
    for (int i = 0; i < 4; i++) {
        int f = i * 256 + tid;
        int r = f >> 4, c4 = f & 15;
        *(float4*)&Ts[r][c4 * 4] =
            *(const float4*)(in + (size_t)(bkr * 64 + r) * N + bnr * 64 + c4 * 4);
    }
    __syncthreads();

#pragma unroll
    for (int i = 0; i < 2; i++) {
        int f    = i * 256 + tid;
        int tile = f >> 5;
        int np   = tile >> 2, kt = tile & 3;
        int l    = f & 31, g = l >> 2, tc = l & 3;
        int r = kt * 16, c = np * 16;
        float4 v;
        v.x = __uint_as_float(h2u(__floats2half2_rn(Ts[r+2*tc  ][c+g  ], Ts[r+2*tc+1][c+g  ])));
        v.y = __uint_as_float(h2u(__floats2half2_rn(Ts[r+2*tc+8][c+g  ], Ts[r+2*tc+9][c+g  ])));
        v.z = __uint_as_float(h2u(__floats2half2_rn(Ts[r+2*tc  ][c+8+g], Ts[r+2*tc+1][c+8+g])));
        v.w = __uint_as_float(h2u(__floats2half2_rn(Ts[r+2*tc+8][c+8+g], Ts[r+2*tc+9][c+8+g])));
        out[((size_t)(bnr * 4 + np) * K16 + (bkr * 4 + kt)) * 32 + l] = v;
    }
}

// ---------------------------------------------------------------------------
// V transpose: g_qkvh V region -> g_vt[b,h,d,t] (proven round-12 kernel).
// ---------------------------------------------------------------------------
__global__ __launch_bounds__(256) void vtrans_kernel(
    const __half* __restrict__ qkvh, __half* __restrict__ vt)
{
    __shared__ __half Ts[64][72];
    const int bt  = blockIdx.x;
    const int h   = blockIdx.y;
    const int b   = blockIdx.z;
    const int tid = threadIdx.x;

#pragma unroll
    for (int i = 0; i < 2; i++) {
        int f = i * 256 + tid;
        int r = f >> 3, c8 = f & 7;
        *(float4*)&Ts[r][c8 * 8] = *(const float4*)(qkvh +
            (size_t)(b * TLEN + bt * 64 + r) * QKVN + 2 * DMOD + h * HDIM + c8 * 8);
    }
    __syncthreads();

#pragma unroll
    for (int i = 0; i < 2; i++) {
        int f = i * 256 + tid;
        int d = f >> 3, t8 = f & 7;
        __half tmp[8];
#pragma unroll
        for (int j = 0; j < 8; j++) tmp[j] = Ts[t8 * 8 + j][d];
        *(float4*)(vt + ((size_t)(b * NHEAD + h) * HDIM + d) * TLEN
                      + bt * 64 + t8 * 8) = *(float4*)tmp;
    }
}

// ---------------------------------------------------------------------------
// fp16 GEMM on fragment-packed operands + bias (fp32 accumulate).
// BM=BN=128, K-slab 64, 256 threads, warp tile 64x32.
// mode 0: fp32 C out. mode 1: half2 row-major out into g_qkvh (uniform path).
// ---------------------------------------------------------------------------
#define GS 3

__global__ __launch_bounds__(256, 2) void gemm_f16(
    const float4* __restrict__ A4, const float4* __restrict__ B4,
    const float* __restrict__ bias, float* __restrict__ C,
    int N, int mode)
{
    extern __shared__ char smem_raw[];

    const int tid   = threadIdx.x;
    const int wid   = tid >> 5, lane = tid & 31;
    const int g     = lane >> 2, tc = lane & 3;
    const int warpM = wid >> 2, warpN = wid & 3;
    const int bm    = blockIdx.y, bn = blockIdx.x;

    const uint32_t sbase = (uint32_t)__cvta_generic_to_shared(smem_raw);
    const uint32_t BOFF  = (uint32_t)(GS * 8 * 4 * 32 * 16);   // 49152 B

    float acc[4][4][4];
#pragma unroll
    for (int mt = 0; mt < 4; mt++)
#pragma unroll
        for (int nt = 0; nt < 4; nt++)
#pragma unroll
            for (int j = 0; j < 4; j++) acc[mt][nt][j] = 0.0f;

    float bias0[4], bias1[4];
#pragma unroll
    for (int nt = 0; nt < 4; nt++) {
        int col = bn * 128 + warpN * 32 + nt * 8 + tc * 2;
        bias0[nt] = bias[col];
        bias1[nt] = bias[col + 1];
    }

    const int nit = K16 / 4;   // 12

#define GEMM_ISSUE(stage)                                                      \
    {                                                                          \
        int _buf = (stage) % GS; int _k4 = (stage) * 4;                        \
        _Pragma("unroll")                                                      \
        for (int i = 0; i < 4; i++) {                                          \
            int f = i * 256 + tid;                                             \
            int mt = f >> 7, kt = (f >> 5) & 3, l = f & 31;                    \
            cp16(sbase + (uint32_t)((((_buf * 8 + mt) * 4 + kt) * 32 + l) * 16),\
                 A4 + ((size_t)(bm * 8 + mt) * K16 + _k4 + kt) * 32 + l);      \
            cp16(sbase + BOFF + (uint32_t)((((_buf * 8 + mt) * 4 + kt) * 32 + l) * 16),\
                 B4 + ((size_t)(bn * 8 + mt) * K16 + _k4 + kt) * 32 + l);      \
        }                                                                      \
        cp_commit();                                                           \
    }

    GEMM_ISSUE(0);
    GEMM_ISSUE(1);

    for (int it = 0; it < nit; it++) {
        if (it + 1 < nit) cp_wait<1>(); else cp_wait<0>();
        __syncthreads();
        if (it + 2 < nit) GEMM_ISSUE(it + 2);

        const int buf = it % GS;
        const float4* Ab4 = (const float4*)smem_raw + (size_t)buf * 8 * 4 * 32;
        const float4* Bb4 = (const float4*)(smem_raw + BOFF) + (size_t)buf * 8 * 4 * 32;

        float4 afv[2][4], bfv[2][2];
#pragma unroll
        for (int mt = 0; mt < 4; mt++)
            afv[0][mt] = Ab4[((warpM * 4 + mt) * 4 + 0) * 32 + lane];
#pragma unroll
        for (int p = 0; p < 2; p++)
            bfv[0][p] = Bb4[((warpN * 2 + p) * 4 + 0) * 32 + lane];

#pragma unroll
        for (int ks = 0; ks < 4; ks++) {
            const int cur = ks & 1;
            if (ks < 3) {
#pragma unroll
                for (int mt = 0; mt < 4; mt++)
                    afv[cur ^ 1][mt] = Ab4[((warpM * 4 + mt) * 4 + ks + 1) * 32 + lane];
#pragma unroll
                for (int p = 0; p < 2; p++)
                    bfv[cur ^ 1][p] = Bb4[((warpN * 2 + p) * 4 + ks + 1) * 32 + lane];
            }
#pragma unroll
            for (int mt = 0; mt < 4; mt++) {
                unsigned a[4];
                a[0] = __float_as_uint(afv[cur][mt].x);
                a[1] = __float_as_uint(afv[cur][mt].y);
                a[2] = __float_as_uint(afv[cur][mt].z);
                a[3] = __float_as_uint(afv[cur][mt].w);
#pragma unroll
                for (int nt = 0; nt < 4; nt++) {
                    const float4& bp = bfv[cur][nt >> 1];
                    unsigned b01 = (nt & 1) ? __float_as_uint(bp.z)
                                            : __float_as_uint(bp.x);
                    unsigned b23 = (nt & 1) ? __float_as_uint(bp.w)
                                            : __float_as_uint(bp.y);
                    mma_f16(acc[mt][nt], a, b01, b23);
                }
            }
        }
    }

    // ---- Epilogue
    if (mode == 0) {
        float* Cb = C + (size_t)bm * 128 * N + bn * 128;
#pragma unroll
        for (int mt = 0; mt < 4; mt++)
#pragma unroll
            for (int nt = 0; nt < 4; nt++) {
                int r0 = warpM * 64 + mt * 16 + g;
                int c0 = warpN * 32 + nt * 8 + tc * 2;
                float2 v0 = make_float2(acc[mt][nt][0] + bias0[nt],
                                        acc[mt][nt][1] + bias1[nt]);
                float2 v1 = make_float2(acc[mt][nt][2] + bias0[nt],
                                        acc[mt][nt][3] + bias1[nt]);
                *(float2*)(Cb + (size_t)r0 * N + c0)       = v0;
                *(float2*)(Cb + (size_t)(r0 + 8) * N + c0) = v1;
            }
    } else {
        // half2 row-major into g_qkvh (uniform for Q, K and V columns)
#pragma unroll
        for (int mt = 0; mt < 4; mt++)
#pragma unroll
            for (int nt = 0; nt < 4; nt++) {
                int r0 = bm * 128 + warpM * 64 + mt * 16 + g;
                int c0 = bn * 128 + warpN * 32 + nt * 8 + tc * 2;
                __half2 v0 = __floats2half2_rn(acc[mt][nt][0] + bias0[nt],
                                               acc[mt][nt][1] + bias1[nt]);
                __half2 v1 = __floats2half2_rn(acc[mt][nt][2] + bias0[nt],
                                               acc[mt][nt][3] + bias1[nt]);
                *(__half2*)&g_qkvh[(size_t)r0 * QKVN + c0]       = v0;
                *(__half2*)&g_qkvh[(size_t)(r0 + 8) * QKVN + c0] = v1;
            }
    }
}

// ---------------------------------------------------------------------------
// Causal flash attention, fp16 mma m16n8k16, fp32 softmax/accumulators.
// Round-12 structure; fragment loads via ldmatrix.x4 (bit-identical math).
// FIX vs round 14: p_lm now includes sbase (was a relative offset -> read
// outside the dynamic smem window -> garbage Q/P fragments).
// ---------------------------------------------------------------------------
#define AS2 72    // halves per smem row (144 B): conflict-free frag loads

struct AttnSmem {
    __half Ks[2][64][AS2];   // 18432 B
    __half Vs[2][64][AS2];   // 18432 B (V transposed: [d][key])
    __half Ps[128][AS2];     // 18432 B (Q staging, then P)
};                           // 55296 B

__global__ __launch_bounds__(256, 2) void attn_f16_kernel(
    const __half* __restrict__ qkvh, const __half* __restrict__ vt,
    float4* __restrict__ outp)
{
    extern __shared__ char smem_raw[];
    AttnSmem& S = *reinterpret_cast<AttnSmem*>(smem_raw);

    const int qb   = (TLEN / 128) - 1 - blockIdx.x;
    const int h    = blockIdx.y;
    const int b    = blockIdx.z;
    const int tid  = threadIdx.x;
    const int wid  = tid >> 5;
    const int lane = tid & 31;
    const int g    = lane >> 2;
    const int tc   = lane & 3;
    const int r0   = wid * 16 + g;
    const int gq0  = qb * 128 + r0;
    const int gq1  = gq0 + 8;

    const uint32_t sbase = (uint32_t)__cvta_generic_to_shared(smem_raw);
    const uint32_t VOFF  = (uint32_t)sizeof(S.Ks);
    const uint32_t POFF  = VOFF + (uint32_t)sizeof(S.Vs);
    const uint32_t KVBUF = (uint32_t)(64 * AS2 * 2);   // 9216 B per buffer

    // ldmatrix lane-base offsets (bytes).
    // K/V (B-frags): m0=(rows lo,col lo) m1=(rows lo,col hi)
    //                m2=(rows hi,col lo) m3=(rows hi,col hi)
    const uint32_t kv_lm = (uint32_t)(
        (((lane >> 4) * 8 + (lane & 7)) * AS2 + ((lane >> 3) & 1) * 8) * 2);
    // P/Q (A-frags): m0=(rows lo,col lo) m1=(rows hi,col lo)
    //                m2=(rows lo,col hi) m3=(rows hi,col hi)
    const uint32_t p_lm = sbase + POFF + (uint32_t)(
        ((wid * 16 + ((lane >> 3) & 1) * 8 + (lane & 7)) * AS2
         + (lane >> 4) * 8) * 2);

#define ATTN_ISSUE(j0, buf)                                                    \
    {                                                                          \
        _Pragma("unroll")                                                      \
        for (int i = 0; i < 4; i++) {                                          \
            int f = i * 256 + tid;                                             \
            int r = (f >> 3) & 63, c8 = f & 7;                                 \
            if (f < 512) {                                                     \
                cp16(sbase + (uint32_t)((((buf) * 64 + r) * AS2 + c8 * 8) * 2),\
                     qkvh + (size_t)(b * TLEN + (j0) + r) * QKVN + DMOD        \
                          + h * HDIM + c8 * 8);                                \
            } else {                                                           \
                cp16(sbase + VOFF + (uint32_t)((((buf) * 64 + r) * AS2 + c8 * 8) * 2),\
                     vt + ((size_t)(b * NHEAD + h) * HDIM + r) * TLEN          \
                        + (j0) + c8 * 8);                                      \
            }                                                                  \
        }                                                                      \
        cp_commit();                                                           \
    }

    // Q staging (same commit group as K/V block 0)
#pragma unroll
    for (int i = 0; i < 4; i++) {
        int f = i * 256 + tid;
        int r = f >> 3, c8 = f & 7;
        cp16(sbase + POFF + (uint32_t)((r * AS2 + c8 * 8) * 2),
             qkvh + (size_t)(b * TLEN + qb * 128 + r) * QKVN + h * HDIM + c8 * 8);
    }
    ATTN_ISSUE(0, 0);

    float oacc[8][4];
#pragma unroll
    for (int n = 0; n < 8; n++)
#pragma unroll
        for (int j = 0; j < 4; j++) oacc[n][j] = 0.0f;
    float m0 = -1e30f, m1 = -1e30f, l0 = 0.0f, l1 = 0.0f;

    const int nblk = 2 * qb + 2;

    // Prologue: prefetch block 1, wait for {Q, KV0}, preload Q fragments
    unsigned qa[4][4];
    {
        ATTN_ISSUE(64, 1);
        cp_wait<1>();
        __syncthreads();
        const __half2 sc = __float2half2_rn(0.125f);   // exact pow2 scale
#pragma unroll
        for (int kk = 0; kk < 4; kk++) {
            unsigned q0, q1, q2, q3;
            ldsm4(q0, q1, q2, q3, p_lm + kk * 32u);
            qa[kk][0] = h2u(__hmul2(*(__half2*)&q0, sc));
            qa[kk][1] = h2u(__hmul2(*(__half2*)&q1, sc));
            qa[kk][2] = h2u(__hmul2(*(__half2*)&q2, sc));
            qa[kk][3] = h2u(__hmul2(*(__half2*)&q3, sc));
        }
        __syncwarp();   // Q rows are warp-private; later P writes are same rows
    }

    for (int kb = 0; kb < nblk; kb++) {
        const int buf = kb & 1;
        const int j0  = kb * 64;

        if (kb > 0) {
            __syncthreads();               // all warps done with buf (prev use)
            if (kb + 1 < nblk) ATTN_ISSUE((kb + 1) * 64, buf ^ 1);
            if (kb + 1 < nblk) cp_wait<1>(); else cp_wait<0>();
            __syncthreads();               // staged data visible to all
        }

        const uint32_t ks_lm = sbase + buf * KVBUF + kv_lm;
        const uint32_t vs_lm = sbase + VOFF + buf * KVBUF + kv_lm;

        // ---- S = Q K^T (fp32 acc in registers), K-frags via ldmatrix
        float sacc[8][4];
#pragma unroll
        for (int n = 0; n < 8; n++)
#pragma unroll
            for (int j = 0; j < 4; j++) sacc[n][j] = 0.0f;

#pragma unroll
        for (int kk = 0; kk < 4; kk++) {
#pragma unroll
            for (int p = 0; p < 4; p++) {
                unsigned b0, b1, b2, b3;
                ldsm4(b0, b1, b2, b3, ks_lm + p * (16u * AS2 * 2) + kk * 32u);
                mma_f16(sacc[2 * p],     qa[kk], b0, b1);
                mma_f16(sacc[2 * p + 1], qa[kk], b2, b3);
            }
        }

        // ---- Causal mask (diagonal blocks only)
        if (kb >= 2 * qb) {
#pragma unroll
            for (int n = 0; n < 8; n++) {
                int col = j0 + n * 8 + tc * 2;
                if (col     > gq0) sacc[n][0] = -1e30f;
                if (col + 1 > gq0) sacc[n][1] = -1e30f;
                if (col     > gq1) sacc[n][2] = -1e30f;
                if (col + 1 > gq1) sacc[n][3] = -1e30f;
            }
        }

        // ---- Online softmax (fp32, register stats)
        float mx0 = -1e30f, mx1 = -1e30f;
#pragma unroll
        for (int n = 0; n < 8; n++) {
            mx0 = fmaxf(mx0, fmaxf(sacc[n][0], sacc[n][1]));
            mx1 = fmaxf(mx1, fmaxf(sacc[n][2], sacc[n][3]));
        }
        mx0 = fmaxf(mx0, __shfl_xor_sync(0xffffffffu, mx0, 1));
        mx0 = fmaxf(mx0, __shfl_xor_sync(0xffffffffu, mx0, 2));
        mx1 = fmaxf(mx1, __shfl_xor_sync(0xffffffffu, mx1, 1));
        mx1 = fmaxf(mx1, __shfl_xor_sync(0xffffffffu, mx1, 2));
        float nm0 = fmaxf(m0, mx0), nm1 = fmaxf(m1, mx1);
        float corr0 = __expf(m0 - nm0), corr1 = __expf(m1 - nm1);
        m0 = nm0; m1 = nm1;

        float sum0 = 0.0f, sum1 = 0.0f;
#pragma unroll
        for (int n = 0; n < 8; n++) {
            float p00 = __expf(sacc[n][0] - m0);
            float p01 = __expf(sacc[n][1] - m0);
            float p10 = __expf(sacc[n][2] - m1);
            float p11 = __expf(sacc[n][3] - m1);
            sum0 += p00 + p01;
            sum1 += p10 + p11;
            *(__half2*)&S.Ps[r0    ][n * 8 + tc * 2] = __floats2half2_rn(p00, p01);
            *(__half2*)&S.Ps[r0 + 8][n * 8 + tc * 2] = __floats2half2_rn(p10, p11);
        }
        sum0 += __shfl_xor_sync(0xffffffffu, sum0, 1);
        sum0 += __shfl_xor_sync(0xffffffffu, sum0, 2);
        sum1 += __shfl_xor_sync(0xffffffffu, sum1, 1);
        sum1 += __shfl_xor_sync(0xffffffffu, sum1, 2);
        l0 = l0 * corr0 + sum0;
        l1 = l1 * corr1 + sum1;

#pragma unroll
        for (int n = 0; n < 8; n++) {
            oacc[n][0] *= corr0; oacc[n][1] *= corr0;
            oacc[n][2] *= corr1; oacc[n][3] *= corr1;
        }
        __syncwarp();                     // P tile is warp-private

        // ---- O += P V, P and V frags via ldmatrix
#pragma unroll
        for (int kk = 0; kk < 4; kk++) {
            unsigned pa[4];
            ldsm4(pa[0], pa[1], pa[2], pa[3], p_lm + kk * 32u);
#pragma unroll
            for (int p = 0; p < 4; p++) {
                unsigned b0, b1, b2, b3;
                ldsm4(b0, b1, b2, b3, vs_lm + p * (16u * AS2 * 2) + kk * 32u);
                mma_f16(oacc[2 * p],     pa, b0, b1);
                mma_f16(oacc[2 * p + 1], pa, b2, b3);
            }
        }
    }

    // ---- Epilogue: normalize, emit GEMM-A fragment-packed half chunks
    {
        float inv0 = 1.0f / l0, inv1 = 1.0f / l1;
        int mt_glob = b * 128 + qb * 8 + wid;
#pragma unroll
        for (int kp = 0; kp < 4; kp++) {
            int n0 = 2 * kp, n1 = 2 * kp + 1;
            float4 v;
            v.x = __uint_as_float(h2u(__floats2half2_rn(oacc[n0][0] * inv0,
                                                        oacc[n0][1] * inv0)));
            v.y = __uint_as_float(h2u(__floats2half2_rn(oacc[n0][2] * inv1,
                                                        oacc[n0][3] * inv1)));
            v.z = __uint_as_float(h2u(__floats2half2_rn(oacc[n1][0] * inv0,
                                                        oacc[n1][1] * inv0)));
            v.w = __uint_as_float(h2u(__floats2half2_rn(oacc[n1][2] * inv1,
                                                        oacc[n1][3] * inv1)));
            int kt_glob = h * 4 + kp;
            outp[((size_t)mt_glob * K16 + kt_glob) * 32 + lane] = v;
        }
    }
}

// ---------------------------------------------------------------------------
// Launch: pack -> QKV GEMM -> V transpose -> attention -> output GEMM.
// ---------------------------------------------------------------------------
extern "C" void kernel_launch(void* const* d_in, const int* in_sizes, int n_in,
                              void* d_out, int out_size)
{
    (void)in_sizes; (void)n_in; (void)out_size;
    const float* x     = (const float*)d_in[0];
    const float* W_qkv = (const float*)d_in[1];
    const float* b_qkv = (const float*)d_in[2];
    const float* W_o   = (const float*)d_in[3];
    const float* b_o   = (const float*)d_in[4];
    float* out = (float*)d_out;

    void *qkvh_p, *vt_p, *xa_p, *ao_p, *wqkv_p, *wo_p;
    cudaGetSymbolAddress(&qkvh_p, g_qkvh);
    cudaGetSymbolAddress(&vt_p,   g_vt);
    cudaGetSymbolAddress(&xa_p,   g_xa);
    cudaGetSymbolAddress(&ao_p,   g_ao);
    cudaGetSymbolAddress(&wqkv_p, g_wqkvh);
    cudaGetSymbolAddress(&wo_p,   g_woh);

    int gemm_smem = GS * 2 * 8 * 4 * 32 * 16;     // 98304 B
    cudaFuncSetAttribute(gemm_f16,
                         cudaFuncAttributeMaxDynamicSharedMemorySize, gemm_smem);
    int attn_smem = (int)sizeof(AttnSmem);
    cudaFuncSetAttribute(attn_f16_kernel,
                         cudaFuncAttributeMaxDynamicSharedMemorySize, attn_smem);

    // 0) pack operands to fp16 fragment layouts
    {
        dim3 ga(DMOD / 64, MROWS / 64);           // (12, 128)
        perm_a_half<<<ga, 256>>>(x, (float4*)xa_p);
        dim3 g1(QKVN / 64, DMOD / 64);            // (36, 12)
        perm_b_half<<<g1, 256>>>(W_qkv, (float4*)wqkv_p, QKVN);
        dim3 g2(DMOD / 64, DMOD / 64);            // (12, 12)
        perm_b_half<<<g2, 256>>>(W_o, (float4*)wo_p, DMOD);
    }
    // 1) qkv = x @ W_qkv + b_qkv -> QKV half row-major
    {
        dim3 grid(QKVN / 128, MROWS / 128);       // (18, 64)
        gemm_f16<<<grid, 256, gemm_smem>>>((const float4*)xa_p,
                                           (const float4*)wqkv_p,
                                           b_qkv, nullptr, QKVN, 1);
    }
    // 1b) transpose V region -> g_vt[b,h,d,t]
    {
        dim3 gv(TLEN / 64, NHEAD, BSZ);           // (32, 12, 4)
        vtrans_kernel<<<gv, 256>>>((const __half*)qkvh_p, (__half*)vt_p);
    }
    // 2) causal flash attention -> packed A operand for GEMM2
    {
        dim3 grid(TLEN / 128, NHEAD, BSZ);        // (16, 12, 4)
        attn_f16_kernel<<<grid, 256, attn_smem>>>((const __half*)qkvh_p,
                                                  (const __half*)vt_p,
                                                  (float4*)ao_p);
    }
    // 3) out = att @ W_o + b_o (fp32 out)
    {
        dim3 grid(DMOD / 128, MROWS / 128);       // (6, 64)
        gemm_f16<<<grid, 256, gemm_smem>>>((const float4*)ao_p,
                                           (const float4*)wo_p,
                                           b_o, out, DMOD, 0);
    }
}